// round 13
// baseline (speedup 1.0000x reference)
#include <cuda_runtime.h>
#include <cuda_bf16.h>
#include <cuda_fp16.h>
#include <cstdint>
#include <math.h>

#define NB 4
#define NS 2048
#define NE 256
#define NH 4
#define ND 64

// Scratch (allocation-free). All seq-indexed arrays in COMPACTED coordinates.
__device__ float g_Q[NB*NH*NS*ND];                                  // [b,h,i,d] fp32
__device__ __align__(16) __half g_Kf[NB*NH*NS*ND];                  // [b,h,i,d] fp16
__device__ __align__(16) __half g_Vf[NB*NH*ND*NS];                  // [b,h,d,i] fp16
__device__ __align__(16) __nv_bfloat16 g_AOh[NB*NH*NS*ND];          // [b,h,i,d]
__device__ __align__(16) __nv_bfloat16 g_AOl[NB*NH*NS*ND];
__device__ __align__(16) __nv_bfloat16 g_Wth[4*NE*NE];              // [mat][n][k]
__device__ __align__(16) __nv_bfloat16 g_Wtl[4*NE*NE];
__device__ __align__(16) __nv_bfloat16 g_Xh[NB*NS*NE];              // [b,i,k] pre-split X
__device__ __align__(16) __nv_bfloat16 g_Xl[NB*NS*NE];
__device__ int g_idx[NB*NS];                                        // compacted -> orig s
__device__ int g_cnt[NB];

__device__ __forceinline__ uint32_t pack_bf16x2(float a, float b) {
    __nv_bfloat162 t = __floats2bfloat162_rn(a, b);   // a -> low half
    return *(uint32_t*)&t;
}
__device__ __forceinline__ uint32_t pack_h2(float a, float b) {
    __half2 t = __floats2half2_rn(a, b);              // a -> low half
    return *(uint32_t*)&t;
}
__device__ __forceinline__ void split_hi_lo(float x, float& hi, float& lo) {
    __nv_bfloat16 h = __float2bfloat16_rn(x);
    hi = __bfloat162float(h);
    lo = x - hi;
}

// mma.sync m16n8k16 row.col (sm_80+ PTX, no arch suffix)
__device__ __forceinline__ void mma16816(float c[4], const uint32_t a[4],
                                         uint32_t b0, uint32_t b1) {
    asm volatile(
        "mma.sync.aligned.m16n8k16.row.col.f32.bf16.bf16.f32 "
        "{%0,%1,%2,%3}, {%4,%5,%6,%7}, {%8,%9}, {%0,%1,%2,%3};"
        : "+f"(c[0]), "+f"(c[1]), "+f"(c[2]), "+f"(c[3])
        : "r"(a[0]), "r"(a[1]), "r"(a[2]), "r"(a[3]), "r"(b0), "r"(b1));
}
__device__ __forceinline__ void mma16816h(float c[4], const uint32_t a[4],
                                          uint32_t b0, uint32_t b1) {
    asm volatile(
        "mma.sync.aligned.m16n8k16.row.col.f32.f16.f16.f32 "
        "{%0,%1,%2,%3}, {%4,%5,%6,%7}, {%8,%9}, {%0,%1,%2,%3};"
        : "+f"(c[0]), "+f"(c[1]), "+f"(c[2]), "+f"(c[3])
        : "r"(a[0]), "r"(a[1]), "r"(a[2]), "r"(a[3]), "r"(b0), "r"(b1));
}

// ldmatrix x4 (sm_75+)
__device__ __forceinline__ void ldsm4(uint32_t r[4], const void* p) {
    uint32_t a = (uint32_t)__cvta_generic_to_shared(p);
    asm volatile("ldmatrix.sync.aligned.m8n8.x4.shared.b16 {%0,%1,%2,%3}, [%4];"
                 : "=r"(r[0]), "=r"(r[1]), "=r"(r[2]), "=r"(r[3]) : "r"(a));
}

// cp.async 16B (sm_80+)
__device__ __forceinline__ void cpa16(void* dst, const void* src) {
    uint32_t d = (uint32_t)__cvta_generic_to_shared(dst);
    asm volatile("cp.async.cg.shared.global [%0], [%1], 16;" :: "r"(d), "l"(src));
}
#define CP_COMMIT() asm volatile("cp.async.commit_group;")
#define CP_WAIT1()  asm volatile("cp.async.wait_group 1;")
#define CP_WAIT0()  asm volatile("cp.async.wait_group 0;")

#define KPAD 72   // 16-bit row stride; 36-word stride -> conflict-free ldmatrix rows
#define S1 (64*KPAD)

// ---------------------------------------------------------------------------
// Kernel A: per-batch compaction index
// ---------------------------------------------------------------------------
__global__ __launch_bounds__(1024) void build_idx(const int* __restrict__ mask)
{
    __shared__ int scan[1024];
    const int b = blockIdx.x;
    const int tid = threadIdx.x;
    const int s0 = 2 * tid, s1 = 2 * tid + 1;
    const int m0 = (mask[b * NS + s0] == 0) ? 1 : 0;
    const int m1 = (mask[b * NS + s1] == 0) ? 1 : 0;
    scan[tid] = m0 + m1;
    __syncthreads();
    #pragma unroll
    for (int off = 1; off < 1024; off <<= 1) {
        int v = (tid >= off) ? scan[tid - off] : 0;
        __syncthreads();
        scan[tid] += v;
        __syncthreads();
    }
    const int excl = scan[tid] - m0 - m1;
    if (m0) g_idx[b * NS + excl] = s0;
    if (m1) g_idx[b * NS + excl + m0] = s1;
    const int total = scan[1023];
    for (int i = tid; i < NS; i += 1024)
        if (i >= total) g_idx[b * NS + i] = 0;
    if (tid == 0) g_cnt[b] = total;
}

// ---------------------------------------------------------------------------
// Kernel A2: gather + pre-split X rows (compacted) -> g_Xh/g_Xl bf16.
// ---------------------------------------------------------------------------
__global__ __launch_bounds__(256) void prep_x(const float* __restrict__ X)
{
    const int m0 = blockIdx.x * 64;
    const int bb = m0 >> 11, loc0 = m0 & (NS - 1);
    const int cnt = g_cnt[bb];
    if (loc0 >= cnt) return;
    const int* idxp = g_idx + bb * NS;
    const int tid = threadIdx.x;

    #pragma unroll
    for (int it = 0; it < 16; it++) {
        int idx = tid + it * 256;
        int r = idx >> 6, c4 = (idx & 63) * 4;
        int src = idxp[loc0 + r];
        float4 v = *(const float4*)(X + ((size_t)bb * NS + src) * NE + c4);
        float h0,l0,h1,l1,h2,l2,h3,l3;
        split_hi_lo(v.x,h0,l0); split_hi_lo(v.y,h1,l1);
        split_hi_lo(v.z,h2,l2); split_hi_lo(v.w,h3,l3);
        size_t o = ((size_t)bb * NS + loc0 + r) * NE + c4;
        uint32_t hw[2] = { pack_bf16x2(h0,h1), pack_bf16x2(h2,h3) };
        uint32_t lw[2] = { pack_bf16x2(l0,l1), pack_bf16x2(l2,l3) };
        *(uint2*)(g_Xh + o) = *(uint2*)hw;
        *(uint2*)(g_Xl + o) = *(uint2*)lw;
    }
}

// ---------------------------------------------------------------------------
// Kernel B: zero all masked output rows (d_out is poisoned).
// ---------------------------------------------------------------------------
__global__ __launch_bounds__(256) void zero_masked(
    const int* __restrict__ mask, float* __restrict__ out)
{
    const int row = blockIdx.x * 4 + (threadIdx.x >> 6);
    const int c4 = threadIdx.x & 63;
    if (mask[row] != 0) {
        float4 z = {0.f, 0.f, 0.f, 0.f};
        *(float4*)(out + (size_t)row * NE + c4 * 4) = z;
    }
}

// ---------------------------------------------------------------------------
// Kernel 0: pre-split weights -> transposed hi/lo bf16 [mat][n][k].
// ---------------------------------------------------------------------------
__global__ __launch_bounds__(256) void prep_w(
    const float* __restrict__ Wq, const float* __restrict__ Wk,
    const float* __restrict__ Wv, const float* __restrict__ Wo)
{
    __shared__ float t[64][65];
    const float* Ws[4] = { Wq, Wk, Wv, Wo };
    const int mt = blockIdx.z;
    const int k0 = blockIdx.x * 64, n0 = blockIdx.y * 64;
    const int tid = threadIdx.x;
    const float* W = Ws[mt];

    #pragma unroll
    for (int it = 0; it < 16; it++) {
        int idx = tid + it * 256;
        int kk = idx >> 6, nn = idx & 63;
        t[kk][nn] = W[(k0 + kk) * NE + n0 + nn];
    }
    __syncthreads();

    #pragma unroll
    for (int it = 0; it < 2; it++) {
        int idx = tid + it * 256;
        int n = idx >> 3, c8 = (idx & 7) * 8;
        uint32_t hw[4], lw[4];
        #pragma unroll
        for (int p = 0; p < 4; p++) {
            float hi0, lo0, hi1, lo1;
            split_hi_lo(t[c8 + 2*p][n],     hi0, lo0);
            split_hi_lo(t[c8 + 2*p + 1][n], hi1, lo1);
            hw[p] = pack_bf16x2(hi0, hi1);
            lw[p] = pack_bf16x2(lo0, lo1);
        }
        size_t o = (size_t)mt * NE * NE + (size_t)(n0 + n) * NE + k0 + c8;
        *(uint4*)(g_Wth + o) = *(uint4*)hw;
        *(uint4*)(g_Wtl + o) = *(uint4*)lw;
    }
}

// ---------------------------------------------------------------------------
// Kernel 1: QKV projection, one weight matrix per blockIdx.z.
// cp.async 2-stage pipeline, ldmatrix fragments.
// Stage layout: Xh | Xl | Wth | Wtl, each 64*KPAD bf16.
// ---------------------------------------------------------------------------
#define QKV_SMEM_BF16 (2 * 4 * S1)    // 2 stages -> 73728 B

__global__ __launch_bounds__(128, 3) void qkv_mma(
    const float* __restrict__ bq, const float* __restrict__ bk,
    const float* __restrict__ bv)
{
    extern __shared__ __nv_bfloat16 smb[];

    const int tid  = threadIdx.x;
    const int w4   = tid >> 5;
    const int lane = tid & 31;
    const int l4   = lane & 3;
    const int matl = lane >> 3;
    const int rowl = lane & 7;
    const int m0   = blockIdx.x * 64;
    const int h    = blockIdx.y;
    const int mt   = blockIdx.z;
    const int n0   = h * 64;

    const int bb   = m0 >> 11;
    const int loc0 = m0 & (NS - 1);
    const int cnt  = g_cnt[bb];
    if (loc0 >= cnt) return;

    const __nv_bfloat16* Xhg = g_Xh + ((size_t)bb * NS + loc0) * NE;
    const __nv_bfloat16* Xlg = g_Xl + ((size_t)bb * NS + loc0) * NE;
    const __nv_bfloat16* Wthg = g_Wth + (size_t)mt * NE * NE + (size_t)n0 * NE;
    const __nv_bfloat16* Wtlg = g_Wtl + (size_t)mt * NE * NE + (size_t)n0 * NE;

    float acc[8][4];
    #pragma unroll
    for (int j = 0; j < 8; j++)
        #pragma unroll
        for (int c = 0; c < 4; c++) acc[j][c] = 0.f;

    const int a_off = (w4 * 16 + (matl & 1) * 8 + rowl) * KPAD + (matl >> 1) * 8;
    const int b_row = (matl >> 1) * 8 + rowl;
    const int b_kh  = (matl & 1) * 8;

    const int ldr = tid >> 3, ldc = (tid & 7) * 8;   // 16 rows per pass of 128 thr

    // ---- pipeline: load stage s for k-chunk k0 ----
    auto load_stage = [&](int s, int k0) {
        __nv_bfloat16* sb = smb + s * 4 * S1;
        #pragma unroll
        for (int it = 0; it < 4; it++) {
            int r = ldr + it * 16;
            cpa16(sb +        r * KPAD + ldc, Xhg  + (size_t)r * NE + k0 + ldc);
            cpa16(sb + S1   + r * KPAD + ldc, Xlg  + (size_t)r * NE + k0 + ldc);
            cpa16(sb + 2*S1 + r * KPAD + ldc, Wthg + (size_t)r * NE + k0 + ldc);
            cpa16(sb + 3*S1 + r * KPAD + ldc, Wtlg + (size_t)r * NE + k0 + ldc);
        }
        CP_COMMIT();
    };

    load_stage(0, 0);
    for (int i = 0; i < 4; i++) {
        if (i < 3) { load_stage((i + 1) & 1, (i + 1) * 64); CP_WAIT1(); }
        else       { CP_WAIT0(); }
        __syncthreads();

        const __nv_bfloat16* sb  = smb + (i & 1) * 4 * S1;
        const __nv_bfloat16* Xh  = sb;
        const __nv_bfloat16* Xl  = sb + S1;
        const __nv_bfloat16* Wth = sb + 2 * S1;
        const __nv_bfloat16* Wtl = sb + 3 * S1;

        #pragma unroll
        for (int kc = 0; kc < 4; kc++) {
            uint32_t ah[4], al[4];
            ldsm4(ah, Xh + a_off + kc * 16);
            ldsm4(al, Xl + a_off + kc * 16);
            #pragma unroll
            for (int jp = 0; jp < 4; jp++) {
                int boff = (jp * 16 + b_row) * KPAD + kc * 16 + b_kh;
                uint32_t bh[4], bl[4];
                ldsm4(bh, Wth + boff);
                ldsm4(bl, Wtl + boff);
                mma16816(acc[2*jp],   ah, bh[0], bh[1]);
                mma16816(acc[2*jp],   al, bh[0], bh[1]);
                mma16816(acc[2*jp],   ah, bl[0], bl[1]);
                mma16816(acc[2*jp+1], ah, bh[2], bh[3]);
                mma16816(acc[2*jp+1], al, bh[2], bh[3]);
                mma16816(acc[2*jp+1], ah, bl[2], bl[3]);
            }
        }
        __syncthreads();
    }

    const int g = lane >> 2;
    const int s0 = loc0 + w4 * 16 + g;
    const int s1 = s0 + 8;

    if (mt == 0) {              // ---- Q: fp32 ----
        float* O0 = g_Q + (((size_t)bb * NH + h) * NS + s0) * ND;
        float* O1 = g_Q + (((size_t)bb * NH + h) * NS + s1) * ND;
        #pragma unroll
        for (int j = 0; j < 8; j++) {
            int d = j * 8 + 2 * l4;
            float bx = bq[n0 + d], by = bq[n0 + d + 1];
            float2 v0 = { acc[j][0] + bx, acc[j][1] + by };
            float2 v1 = { acc[j][2] + bx, acc[j][3] + by };
            *(float2*)(O0 + d) = v0;
            *(float2*)(O1 + d) = v1;
        }
    } else if (mt == 1) {       // ---- K: fp16 ----
        size_t o0 = (((size_t)bb * NH + h) * NS + s0) * ND;
        size_t o1 = (((size_t)bb * NH + h) * NS + s1) * ND;
        #pragma unroll
        for (int j = 0; j < 8; j++) {
            int d = j * 8 + 2 * l4;
            float bx = bk[n0 + d], by = bk[n0 + d + 1];
            *(uint32_t*)(g_Kf + o0 + d) = pack_h2(acc[j][0] + bx, acc[j][1] + by);
            *(uint32_t*)(g_Kf + o1 + d) = pack_h2(acc[j][2] + bx, acc[j][3] + by);
        }
    } else {                    // ---- V: transpose via smem, fp16 [b,h,d,i] ----
        #define VPAD 68
        float* Vb = (float*)smb;
        #pragma unroll
        for (int j = 0; j < 8; j++) {
            int d = j * 8 + 2 * l4;
            float bx = bv[n0 + d], by = bv[n0 + d + 1];
            int sr0 = w4 * 16 + g, sr1 = sr0 + 8;
            Vb[(d    ) * VPAD + sr0] = acc[j][0] + bx;
            Vb[(d + 1) * VPAD + sr0] = acc[j][1] + by;
            Vb[(d    ) * VPAD + sr1] = acc[j][2] + bx;
            Vb[(d + 1) * VPAD + sr1] = acc[j][3] + by;
        }
        __syncthreads();
        #pragma unroll
        for (int it = 0; it < 8; it++) {
            int idx = tid + it * 128;
            int d = idx >> 4, c4 = (idx & 15) * 4;
            int s = loc0 + c4;
            size_t o = (((size_t)bb * NH + h) * ND + d) * NS + s;
            uint32_t hw[2] = { pack_h2(Vb[d * VPAD + c4],     Vb[d * VPAD + c4 + 1]),
                               pack_h2(Vb[d * VPAD + c4 + 2], Vb[d * VPAD + c4 + 3]) };
            *(uint2*)(g_Vf + o) = *(uint2*)hw;
        }
    }
}

// ---------------------------------------------------------------------------
// Kernel 2: flash attention, q-tile 64, 2 warpgroups split over K-tiles.
// ---------------------------------------------------------------------------
__global__ __launch_bounds__(256, 2) void attn_mma(
    const float* __restrict__ explore,
    const float* __restrict__ exploit)
{
    __shared__ __align__(16) __half Ks[2][64*KPAD];
    __shared__ __align__(16) __half Vs[2][64*KPAD];
    __shared__ float pens[2][64];

    const int tid  = threadIdx.x;
    const int w    = tid >> 5;
    const int wg   = w >> 2;
    const int w4   = w & 3;
    const int wtid = tid & 127;
    const int lane = tid & 31;
    const int g    = lane >> 2;
    const int l4   = lane & 3;
    const int matl = lane >> 3;
    const int rowl = lane & 7;
    const int q0   = blockIdx.x * 64;
    const int h    = blockIdx.y, b = blockIdx.z;

    const int cnt = g_cnt[b];
    if (q0 >= cnt) return;
    const int* idxp = g_idx + b * NS;
    const int NT = (cnt + 63) >> 6;

    const size_t base = ((size_t)b * NH + h) * NS * ND;
    const float* Qp = g_Q + base;
    const __half* Kp = g_Kf + base;
    const __half* Vp = g_Vf + base;

    const int r0 = w4 * 16 + g;
    const int r1 = r0 + 8;
    const int cq0 = q0 + r0, cq1 = q0 + r1;
    const int so0 = idxp[cq0], so1 = idxp[cq1];
    float rs0, rs1;
    {
        float t0 = 1.0f + 0.5f * explore[b * NS + so0] - 0.5f * exploit[b * NS + so0];
        t0 = fminf(fmaxf(t0, 0.5f), 2.0f);
        rs0 = 0.125f / t0;
        float t1 = 1.0f + 0.5f * explore[b * NS + so1] - 0.5f * exploit[b * NS + so1];
        t1 = fminf(fmaxf(t1, 0.5f), 2.0f);
        rs1 = 0.125f / t1;
    }

    uint32_t qf[4][4];
    #pragma unroll
    for (int kc = 0; kc < 4; kc++) {
        int d0 = kc * 16 + l4 * 2;
        const float2 a00 = *(const float2*)(Qp + (size_t)cq0 * ND + d0);
        const float2 a10 = *(const float2*)(Qp + (size_t)cq1 * ND + d0);
        const float2 a01 = *(const float2*)(Qp + (size_t)cq0 * ND + d0 + 8);
        const float2 a11 = *(const float2*)(Qp + (size_t)cq1 * ND + d0 + 8);
        qf[kc][0] = pack_h2(a00.x * rs0, a00.y * rs0);
        qf[kc][1] = pack_h2(a10.x * rs1, a10.y * rs1);
        qf[kc][2] = pack_h2(a01.x * rs0, a01.y * rs0);
        qf[kc][3] = pack_h2(a11.x * rs1, a11.y * rs1);
    }

    float oacc[8][4];
    #pragma unroll
    for (int j = 0; j < 8; j++)
        #pragma unroll
        for (int c = 0; c < 4; c++) oacc[j][c] = 0.f;
    float lsum0 = 0.f, lsum1 = 0.f;

    __half* Ksw = Ks[wg];
    __half* Vsw = Vs[wg];
    const int b_row = (matl >> 1) * 8 + rowl;
    const int b_kh  = (matl & 1) * 8;

    for (int kt = wg; kt < NT; kt += 2) {
        const int kk0 = kt * 64;

        #pragma unroll
        for (int it = 0; it < 4; it++) {
            int idx = wtid + it * 128;
            int r = idx >> 3, c8 = (idx & 7) * 8;
            *(uint4*)(Ksw + r * KPAD + c8) = *(const uint4*)(Kp + (size_t)(kk0 + r) * ND + c8);
            *(uint4*)(Vsw + r * KPAD + c8) = *(const uint4*)(Vp + (size_t)r * NS + kk0 + c8);
        }
        if (wtid < 64) pens[wg][wtid] = (kk0 + wtid < cnt) ? -11.0f : -1e30f;
        asm volatile("bar.sync %0, %1;" :: "r"(wg + 1), "r"(128) : "memory");

        float sacc[8][4];
        #pragma unroll
        for (int j = 0; j < 8; j++)
            #pragma unroll
            for (int c = 0; c < 4; c++) sacc[j][c] = 0.f;

        #pragma unroll
        for (int kc = 0; kc < 4; kc++) {
            #pragma unroll
            for (int jp = 0; jp < 4; jp++) {
                uint32_t kb[4];
                ldsm4(kb, Ksw + (jp * 16 + b_row) * KPAD + kc * 16 + b_kh);
                mma16816h(sacc[2*jp],   qf[kc], kb[0], kb[1]);
                mma16816h(sacc[2*jp+1], qf[kc], kb[2], kb[3]);
            }
        }

        uint32_t ps[8][2];
        #pragma unroll
        for (int j = 0; j < 8; j++) {
            float2 pen2 = *(const float2*)(&pens[wg][j * 8 + l4 * 2]);
            float p0 = __expf(sacc[j][0] + pen2.x);
            float p1 = __expf(sacc[j][1] + pen2.y);
            float p2 = __expf(sacc[j][2] + pen2.x);
            float p3 = __expf(sacc[j][3] + pen2.y);
            lsum0 += p0 + p1;
            lsum1 += p2 + p3;
            ps[j][0] = pack_h2(p0, p1);
            ps[j][1] = pack_h2(p2, p3);
        }

        #pragma unroll
        for (int kc = 0; kc < 4; kc++) {
            uint32_t Af[4] = { ps[2*kc][0], ps[2*kc][1], ps[2*kc+1][0], ps[2*kc+1][1] };
            #pragma unroll
            for (int jp = 0; jp < 4; jp++) {
                uint32_t vb[4];
                ldsm4(vb, Vsw + (jp * 16 + b_row) * KPAD + kc * 16 + b_kh);
                mma16816h(oacc[2*jp],   Af, vb[0], vb[1]);
                mma16816h(oacc[2*jp+1], Af, vb[2], vb[3]);
            }
        }
        asm volatile("bar.sync %0, %1;" :: "r"(wg + 1), "r"(128) : "memory");
    }

    lsum0 += __shfl_xor_sync(0xffffffffu, lsum0, 1);
    lsum0 += __shfl_xor_sync(0xffffffffu, lsum0, 2);
    lsum1 += __shfl_xor_sync(0xffffffffu, lsum1, 1);
    lsum1 += __shfl_xor_sync(0xffffffffu, lsum1, 2);

    __syncthreads();
    float* Ob = (float*)&Ks[0][0];
    float* Lb = Ob + 64 * 66;
    if (wg == 1) {
        #pragma unroll
        for (int j = 0; j < 8; j++) {
            int col = j * 8 + 2 * l4;
            Ob[r0 * 66 + col]     = oacc[j][0];
            Ob[r0 * 66 + col + 1] = oacc[j][1];
            Ob[r1 * 66 + col]     = oacc[j][2];
            Ob[r1 * 66 + col + 1] = oacc[j][3];
        }
        if (l4 == 0) { Lb[r0] = lsum0; Lb[r1] = lsum1; }
    }
    __syncthreads();
    if (wg == 0) {
        lsum0 += Lb[r0];
        lsum1 += Lb[r1];
        float inv0 = (lsum0 > 0.f) ? 1.f / lsum0 : 0.f;
        float inv1 = (lsum1 > 0.f) ? 1.f / lsum1 : 0.f;
        if (cq0 < cnt) {
            size_t o0 = base + (size_t)cq0 * ND;
            #pragma unroll
            for (int j = 0; j < 8; j++) {
                int col = j * 8 + 2 * l4;
                float v0 = (oacc[j][0] + Ob[r0 * 66 + col])     * inv0;
                float v1 = (oacc[j][1] + Ob[r0 * 66 + col + 1]) * inv0;
                float h0,l0,h1,l1;
                split_hi_lo(v0, h0, l0); split_hi_lo(v1, h1, l1);
                *(uint32_t*)(g_AOh + o0 + col) = pack_bf16x2(h0, h1);
                *(uint32_t*)(g_AOl + o0 + col) = pack_bf16x2(l0, l1);
            }
        }
        if (cq1 < cnt) {
            size_t o1 = base + (size_t)cq1 * ND;
            #pragma unroll
            for (int j = 0; j < 8; j++) {
                int col = j * 8 + 2 * l4;
                float v0 = (oacc[j][2] + Ob[r1 * 66 + col])     * inv1;
                float v1 = (oacc[j][3] + Ob[r1 * 66 + col + 1]) * inv1;
                float h0,l0,h1,l1;
                split_hi_lo(v0, h0, l0); split_hi_lo(v1, h1, l1);
                *(uint32_t*)(g_AOh + o1 + col) = pack_bf16x2(h0, h1);
                *(uint32_t*)(g_AOl + o1 + col) = pack_bf16x2(l0, l1);
            }
        }
    }
}

// ---------------------------------------------------------------------------
// Kernel 3: output projection, cp.async 2-stage pipeline, compacted rows.
// ---------------------------------------------------------------------------
#define OP_SMEM_BF16 (2 * 4 * S1)    // 73728 B

__global__ __launch_bounds__(128, 3) void out_proj_mma(
    const float* __restrict__ bo,
    float* __restrict__ out)
{
    extern __shared__ __nv_bfloat16 smb[];

    const int tid  = threadIdx.x;
    const int w4   = tid >> 5;
    const int lane = tid & 31;
    const int l4   = lane & 3;
    const int matl = lane >> 3;
    const int rowl = lane & 7;
    const int m0   = blockIdx.x * 64;
    const int n0   = blockIdx.y * 64;

    const int bb   = m0 >> 11;
    const int loc0 = m0 & (NS - 1);
    const int cnt  = g_cnt[bb];
    if (loc0 >= cnt) return;
    const int* idxp = g_idx + bb * NS;

    const __nv_bfloat16* Wthg = g_Wth + (size_t)3 * NE * NE + (size_t)n0 * NE;
    const __nv_bfloat16* Wtlg = g_Wtl + (size_t)3 * NE * NE + (size_t)n0 * NE;

    float acc[8][4];
    #pragma unroll
    for (int j = 0; j < 8; j++)
        #pragma unroll
        for (int c = 0; c < 4; c++) acc[j][c] = 0.f;

    const int a_off = (w4 * 16 + (matl & 1) * 8 + rowl) * KPAD + (matl >> 1) * 8;
    const int b_row = (matl >> 1) * 8 + rowl;
    const int b_kh  = (matl & 1) * 8;
    const int ldr = tid >> 3, ldc = (tid & 7) * 8;

    auto load_stage = [&](int s, int k0) {
        __nv_bfloat16* sb = smb + s * 4 * S1;
        const int hh = k0 >> 6;
        const __nv_bfloat16* Ah = g_AOh + (((size_t)bb * NH + hh) * NS + loc0) * ND;
        const __nv_bfloat16* Al = g_AOl + (((size_t)bb * NH + hh) * NS + loc0) * ND;
        #pragma unroll
        for (int it = 0; it < 4; it++) {
            int r = ldr + it * 16;
            cpa16(sb +        r * KPAD + ldc, Ah + (size_t)r * ND + ldc);
            cpa16(sb + S1   + r * KPAD + ldc, Al + (size_t)r * ND + ldc);
            cpa16(sb + 2*S1 + r * KPAD + ldc, Wthg + (size_t)r * NE + k0 + ldc);
            cpa16(sb + 3*S1 + r * KPAD + ldc, Wtlg + (size_t)r * NE + k0 + ldc);
        }
        CP_COMMIT();
    };

    load_stage(0, 0);
    for (int i = 0; i < 4; i++) {
        if (i < 3) { load_stage((i + 1) & 1, (i + 1) * 64); CP_WAIT1(); }
        else       { CP_WAIT0(); }
        __syncthreads();

        const __nv_bfloat16* sb  = smb + (i & 1) * 4 * S1;
        const __nv_bfloat16* Xh  = sb;
        const __nv_bfloat16* Xl  = sb + S1;
        const __nv_bfloat16* Wth = sb + 2 * S1;
        const __nv_bfloat16* Wtl = sb + 3 * S1;

        #pragma unroll
        for (int kc = 0; kc < 4; kc++) {
            uint32_t ah[4], al[4];
            ldsm4(ah, Xh + a_off + kc * 16);
            ldsm4(al, Xl + a_off + kc * 16);
            #pragma unroll
            for (int jp = 0; jp < 4; jp++) {
                int boff = (jp * 16 + b_row) * KPAD + kc * 16 + b_kh;
                uint32_t bh[4], bl[4];
                ldsm4(bh, Wth + boff);
                ldsm4(bl, Wtl + boff);
                mma16816(acc[2*jp],   ah, bh[0], bh[1]);
                mma16816(acc[2*jp],   al, bh[0], bh[1]);
                mma16816(acc[2*jp],   ah, bl[0], bl[1]);
                mma16816(acc[2*jp+1], ah, bh[2], bh[3]);
                mma16816(acc[2*jp+1], al, bh[2], bh[3]);
                mma16816(acc[2*jp+1], ah, bl[2], bl[3]);
            }
        }
        __syncthreads();
    }

    const int g = lane >> 2;
    const int lr0 = loc0 + w4 * 16 + g;
    const int lr1 = lr0 + 8;
    if (lr0 < cnt) {
        int row = bb * NS + idxp[lr0];
        #pragma unroll
        for (int j = 0; j < 8; j++) {
            int d = j * 8 + 2 * l4;
            float2 v = { acc[j][0] + bo[n0 + d], acc[j][1] + bo[n0 + d + 1] };
            *(float2*)(out + (size_t)row * NE + n0 + d) = v;
        }
    }
    if (lr1 < cnt) {
        int row = bb * NS + idxp[lr1];
        #pragma unroll
        for (int j = 0; j < 8; j++) {
            int d = j * 8 + 2 * l4;
            float2 v = { acc[j][2] + bo[n0 + d], acc[j][3] + bo[n0 + d + 1] };
            *(float2*)(out + (size_t)row * NE + n0 + d) = v;
        }
    }
}

// ---------------------------------------------------------------------------
extern "C" void kernel_launch(void* const* d_in, const int* in_sizes, int n_in,
                              void* d_out, int out_size)
{
    const float* his     = (const float*)d_in[0];
    const int*   mask    = (const int*)d_in[1];
    const float* explore = (const float*)d_in[2];
    const float* exploit = (const float*)d_in[3];
    const float* Wq = (const float*)d_in[4];
    const float* bq = (const float*)d_in[5];
    const float* Wk = (const float*)d_in[6];
    const float* bk = (const float*)d_in[7];
    const float* Wv = (const float*)d_in[8];
    const float* bv = (const float*)d_in[9];
    const float* Wo = (const float*)d_in[10];
    const float* bo = (const float*)d_in[11];
    float* out = (float*)d_out;

    const int qkv_smem = QKV_SMEM_BF16 * 2;     // 73728 B
    const int op_smem  = OP_SMEM_BF16 * 2;      // 73728 B
    static cudaStream_t s2 = nullptr, s3 = nullptr;
    static cudaEvent_t ev_root = nullptr, ev_w = nullptr, ev_z = nullptr;
    if (s2 == nullptr) {
        cudaFuncSetAttribute(qkv_mma, cudaFuncAttributeMaxDynamicSharedMemorySize, qkv_smem);
        cudaFuncSetAttribute(out_proj_mma, cudaFuncAttributeMaxDynamicSharedMemorySize, op_smem);
        cudaStreamCreateWithFlags(&s2, cudaStreamNonBlocking);
        cudaStreamCreateWithFlags(&s3, cudaStreamNonBlocking);
        cudaEventCreateWithFlags(&ev_root, cudaEventDisableTiming);
        cudaEventCreateWithFlags(&ev_w, cudaEventDisableTiming);
        cudaEventCreateWithFlags(&ev_z, cudaEventDisableTiming);
    }

    // fork: prep_w on s2, zero_masked on s3, build_idx + prep_x on main
    cudaEventRecord(ev_root, 0);
    cudaStreamWaitEvent(s2, ev_root, 0);
    cudaStreamWaitEvent(s3, ev_root, 0);
    prep_w<<<dim3(4, 4, 4), 256, 0, s2>>>(Wq, Wk, Wv, Wo);
    zero_masked<<<NB * NS / 4, 256, 0, s3>>>(mask, out);
    build_idx<<<NB, 1024>>>(mask);
    prep_x<<<NB * NS / 64, 256>>>(his);

    // join prep_w before qkv (needs g_Wth/g_Wtl)
    cudaEventRecord(ev_w, s2);
    cudaStreamWaitEvent(0, ev_w, 0);
    qkv_mma<<<dim3(NB * NS / 64, NH, 3), 128, qkv_smem>>>(bq, bk, bv);
    attn_mma<<<dim3(NS / 64, NH, NB), 256>>>(explore, exploit);

    // join zero_masked before out_proj (both write `out`, disjoint rows)
    cudaEventRecord(ev_z, s3);
    cudaStreamWaitEvent(0, ev_z, 0);
    out_proj_mma<<<dim3(NB * NS / 64, 4), 128, op_smem>>>(bo, out);
}

// round 14
// speedup vs baseline: 1.0583x; 1.0583x over previous
#include <cuda_runtime.h>
#include <cuda_bf16.h>
#include <cuda_fp16.h>
#include <cstdint>
#include <math.h>

#define NB 4
#define NS 2048
#define NE 256
#define NH 4
#define ND 64

// Scratch (allocation-free). All seq-indexed arrays in COMPACTED coordinates.
__device__ float g_Q[NB*NH*NS*ND];                                  // [b,h,i,d] fp32
__device__ __align__(16) __half g_Kf[NB*NH*NS*ND];                  // [b,h,i,d] fp16
__device__ __align__(16) __half g_Vf[NB*NH*ND*NS];                  // [b,h,d,i] fp16
__device__ __align__(16) __nv_bfloat16 g_AOh[NB*NH*NS*ND];          // [b,h,i,d]
__device__ __align__(16) __nv_bfloat16 g_AOl[NB*NH*NS*ND];
__device__ __align__(16) __nv_bfloat16 g_Wth[4*NE*NE];              // [mat][n][k]
__device__ __align__(16) __nv_bfloat16 g_Wtl[4*NE*NE];
__device__ __align__(16) __nv_bfloat16 g_Xh[NB*NS*NE];              // [b,i,k] pre-split X
__device__ __align__(16) __nv_bfloat16 g_Xl[NB*NS*NE];
__device__ int g_idx[NB*NS];                                        // compacted -> orig s
__device__ int g_cnt[NB];

__device__ __forceinline__ uint32_t pack_bf16x2(float a, float b) {
    __nv_bfloat162 t = __floats2bfloat162_rn(a, b);   // a -> low half
    return *(uint32_t*)&t;
}
__device__ __forceinline__ uint32_t pack_h2(float a, float b) {
    __half2 t = __floats2half2_rn(a, b);              // a -> low half
    return *(uint32_t*)&t;
}
__device__ __forceinline__ void split_hi_lo(float x, float& hi, float& lo) {
    __nv_bfloat16 h = __float2bfloat16_rn(x);
    hi = __bfloat162float(h);
    lo = x - hi;
}

// mma.sync m16n8k16 row.col (sm_80+ PTX, no arch suffix)
__device__ __forceinline__ void mma16816(float c[4], const uint32_t a[4],
                                         uint32_t b0, uint32_t b1) {
    asm volatile(
        "mma.sync.aligned.m16n8k16.row.col.f32.bf16.bf16.f32 "
        "{%0,%1,%2,%3}, {%4,%5,%6,%7}, {%8,%9}, {%0,%1,%2,%3};"
        : "+f"(c[0]), "+f"(c[1]), "+f"(c[2]), "+f"(c[3])
        : "r"(a[0]), "r"(a[1]), "r"(a[2]), "r"(a[3]), "r"(b0), "r"(b1));
}
__device__ __forceinline__ void mma16816h(float c[4], const uint32_t a[4],
                                          uint32_t b0, uint32_t b1) {
    asm volatile(
        "mma.sync.aligned.m16n8k16.row.col.f32.f16.f16.f32 "
        "{%0,%1,%2,%3}, {%4,%5,%6,%7}, {%8,%9}, {%0,%1,%2,%3};"
        : "+f"(c[0]), "+f"(c[1]), "+f"(c[2]), "+f"(c[3])
        : "r"(a[0]), "r"(a[1]), "r"(a[2]), "r"(a[3]), "r"(b0), "r"(b1));
}

// ldmatrix x4 (sm_75+)
__device__ __forceinline__ void ldsm4(uint32_t r[4], const void* p) {
    uint32_t a = (uint32_t)__cvta_generic_to_shared(p);
    asm volatile("ldmatrix.sync.aligned.m8n8.x4.shared.b16 {%0,%1,%2,%3}, [%4];"
                 : "=r"(r[0]), "=r"(r[1]), "=r"(r[2]), "=r"(r[3]) : "r"(a));
}

// cp.async 16B (sm_80+)
__device__ __forceinline__ void cpa16(void* dst, const void* src) {
    uint32_t d = (uint32_t)__cvta_generic_to_shared(dst);
    asm volatile("cp.async.cg.shared.global [%0], [%1], 16;" :: "r"(d), "l"(src));
}
#define CP_COMMIT() asm volatile("cp.async.commit_group;")
#define CP_WAIT1()  asm volatile("cp.async.wait_group 1;")
#define CP_WAIT0()  asm volatile("cp.async.wait_group 0;")

#define KPAD 72   // 16-bit row stride; 36-word stride -> conflict-free ldmatrix rows
#define S1 (64*KPAD)

// ---------------------------------------------------------------------------
// Kernel A: per-batch compaction index
// ---------------------------------------------------------------------------
__global__ __launch_bounds__(1024) void build_idx(const int* __restrict__ mask)
{
    __shared__ int scan[1024];
    const int b = blockIdx.x;
    const int tid = threadIdx.x;
    const int s0 = 2 * tid, s1 = 2 * tid + 1;
    const int m0 = (mask[b * NS + s0] == 0) ? 1 : 0;
    const int m1 = (mask[b * NS + s1] == 0) ? 1 : 0;
    scan[tid] = m0 + m1;
    __syncthreads();
    #pragma unroll
    for (int off = 1; off < 1024; off <<= 1) {
        int v = (tid >= off) ? scan[tid - off] : 0;
        __syncthreads();
        scan[tid] += v;
        __syncthreads();
    }
    const int excl = scan[tid] - m0 - m1;
    if (m0) g_idx[b * NS + excl] = s0;
    if (m1) g_idx[b * NS + excl + m0] = s1;
    const int total = scan[1023];
    for (int i = tid; i < NS; i += 1024)
        if (i >= total) g_idx[b * NS + i] = 0;
    if (tid == 0) g_cnt[b] = total;
}

// ---------------------------------------------------------------------------
// Kernel A2: gather + pre-split X rows (compacted) -> g_Xh/g_Xl bf16.
// 16 rows/block, 512 blocks -> enough warps to hide gather latency.
// ---------------------------------------------------------------------------
__global__ __launch_bounds__(256) void prep_x(const float* __restrict__ X)
{
    const int m0 = blockIdx.x * 16;
    const int bb = m0 >> 11, loc0 = m0 & (NS - 1);
    const int cnt = g_cnt[bb];
    if (loc0 >= cnt) return;
    const int* idxp = g_idx + bb * NS;
    const int tid = threadIdx.x;

    #pragma unroll
    for (int it = 0; it < 4; it++) {
        int idx = tid + it * 256;
        int r = idx >> 6, c4 = (idx & 63) * 4;
        int src = idxp[loc0 + r];
        float4 v = *(const float4*)(X + ((size_t)bb * NS + src) * NE + c4);
        float h0,l0,h1,l1,h2,l2,h3,l3;
        split_hi_lo(v.x,h0,l0); split_hi_lo(v.y,h1,l1);
        split_hi_lo(v.z,h2,l2); split_hi_lo(v.w,h3,l3);
        size_t o = ((size_t)bb * NS + loc0 + r) * NE + c4;
        uint32_t hw[2] = { pack_bf16x2(h0,h1), pack_bf16x2(h2,h3) };
        uint32_t lw[2] = { pack_bf16x2(l0,l1), pack_bf16x2(l2,l3) };
        *(uint2*)(g_Xh + o) = *(uint2*)hw;
        *(uint2*)(g_Xl + o) = *(uint2*)lw;
    }
}

// ---------------------------------------------------------------------------
// Kernel B: zero all masked output rows (d_out is poisoned).
// ---------------------------------------------------------------------------
__global__ __launch_bounds__(256) void zero_masked(
    const int* __restrict__ mask, float* __restrict__ out)
{
    const int row = blockIdx.x * 4 + (threadIdx.x >> 6);
    const int c4 = threadIdx.x & 63;
    if (mask[row] != 0) {
        float4 z = {0.f, 0.f, 0.f, 0.f};
        *(float4*)(out + (size_t)row * NE + c4 * 4) = z;
    }
}

// ---------------------------------------------------------------------------
// Kernel 0: pre-split weights -> transposed hi/lo bf16 [mat][n][k].
// ---------------------------------------------------------------------------
__global__ __launch_bounds__(256) void prep_w(
    const float* __restrict__ Wq, const float* __restrict__ Wk,
    const float* __restrict__ Wv, const float* __restrict__ Wo)
{
    __shared__ float t[64][65];
    const float* Ws[4] = { Wq, Wk, Wv, Wo };
    const int mt = blockIdx.z;
    const int k0 = blockIdx.x * 64, n0 = blockIdx.y * 64;
    const int tid = threadIdx.x;
    const float* W = Ws[mt];

    #pragma unroll
    for (int it = 0; it < 16; it++) {
        int idx = tid + it * 256;
        int kk = idx >> 6, nn = idx & 63;
        t[kk][nn] = W[(k0 + kk) * NE + n0 + nn];
    }
    __syncthreads();

    #pragma unroll
    for (int it = 0; it < 2; it++) {
        int idx = tid + it * 256;
        int n = idx >> 3, c8 = (idx & 7) * 8;
        uint32_t hw[4], lw[4];
        #pragma unroll
        for (int p = 0; p < 4; p++) {
            float hi0, lo0, hi1, lo1;
            split_hi_lo(t[c8 + 2*p][n],     hi0, lo0);
            split_hi_lo(t[c8 + 2*p + 1][n], hi1, lo1);
            hw[p] = pack_bf16x2(hi0, hi1);
            lw[p] = pack_bf16x2(lo0, lo1);
        }
        size_t o = (size_t)mt * NE * NE + (size_t)(n0 + n) * NE + k0 + c8;
        *(uint4*)(g_Wth + o) = *(uint4*)hw;
        *(uint4*)(g_Wtl + o) = *(uint4*)lw;
    }
}

// ---------------------------------------------------------------------------
// Kernel 1: QKV projection, one weight matrix per blockIdx.z.
// cp.async 2-stage pipeline, ldmatrix fragments.
// ---------------------------------------------------------------------------
#define QKV_SMEM_BF16 (2 * 4 * S1)    // 2 stages -> 73728 B

__global__ __launch_bounds__(128, 3) void qkv_mma(
    const float* __restrict__ bq, const float* __restrict__ bk,
    const float* __restrict__ bv)
{
    extern __shared__ __nv_bfloat16 smb[];

    const int tid  = threadIdx.x;
    const int w4   = tid >> 5;
    const int lane = tid & 31;
    const int l4   = lane & 3;
    const int matl = lane >> 3;
    const int rowl = lane & 7;
    const int m0   = blockIdx.x * 64;
    const int h    = blockIdx.y;
    const int mt   = blockIdx.z;
    const int n0   = h * 64;

    const int bb   = m0 >> 11;
    const int loc0 = m0 & (NS - 1);
    const int cnt  = g_cnt[bb];
    if (loc0 >= cnt) return;

    const __nv_bfloat16* Xhg = g_Xh + ((size_t)bb * NS + loc0) * NE;
    const __nv_bfloat16* Xlg = g_Xl + ((size_t)bb * NS + loc0) * NE;
    const __nv_bfloat16* Wthg = g_Wth + (size_t)mt * NE * NE + (size_t)n0 * NE;
    const __nv_bfloat16* Wtlg = g_Wtl + (size_t)mt * NE * NE + (size_t)n0 * NE;

    float acc[8][4];
    #pragma unroll
    for (int j = 0; j < 8; j++)
        #pragma unroll
        for (int c = 0; c < 4; c++) acc[j][c] = 0.f;

    const int a_off = (w4 * 16 + (matl & 1) * 8 + rowl) * KPAD + (matl >> 1) * 8;
    const int b_row = (matl >> 1) * 8 + rowl;
    const int b_kh  = (matl & 1) * 8;

    const int ldr = tid >> 3, ldc = (tid & 7) * 8;

    auto load_stage = [&](int s, int k0) {
        __nv_bfloat16* sb = smb + s * 4 * S1;
        #pragma unroll
        for (int it = 0; it < 4; it++) {
            int r = ldr + it * 16;
            cpa16(sb +        r * KPAD + ldc, Xhg  + (size_t)r * NE + k0 + ldc);
            cpa16(sb + S1   + r * KPAD + ldc, Xlg  + (size_t)r * NE + k0 + ldc);
            cpa16(sb + 2*S1 + r * KPAD + ldc, Wthg + (size_t)r * NE + k0 + ldc);
            cpa16(sb + 3*S1 + r * KPAD + ldc, Wtlg + (size_t)r * NE + k0 + ldc);
        }
        CP_COMMIT();
    };

    load_stage(0, 0);
    for (int i = 0; i < 4; i++) {
        if (i < 3) { load_stage((i + 1) & 1, (i + 1) * 64); CP_WAIT1(); }
        else       { CP_WAIT0(); }
        __syncthreads();

        const __nv_bfloat16* sb  = smb + (i & 1) * 4 * S1;
        const __nv_bfloat16* Xh  = sb;
        const __nv_bfloat16* Xl  = sb + S1;
        const __nv_bfloat16* Wth = sb + 2 * S1;
        const __nv_bfloat16* Wtl = sb + 3 * S1;

        #pragma unroll
        for (int kc = 0; kc < 4; kc++) {
            uint32_t ah[4], al[4];
            ldsm4(ah, Xh + a_off + kc * 16);
            ldsm4(al, Xl + a_off + kc * 16);
            #pragma unroll
            for (int jp = 0; jp < 4; jp++) {
                int boff = (jp * 16 + b_row) * KPAD + kc * 16 + b_kh;
                uint32_t bh[4], bl[4];
                ldsm4(bh, Wth + boff);
                ldsm4(bl, Wtl + boff);
                mma16816(acc[2*jp],   ah, bh[0], bh[1]);
                mma16816(acc[2*jp],   al, bh[0], bh[1]);
                mma16816(acc[2*jp],   ah, bl[0], bl[1]);
                mma16816(acc[2*jp+1], ah, bh[2], bh[3]);
                mma16816(acc[2*jp+1], al, bh[2], bh[3]);
                mma16816(acc[2*jp+1], ah, bl[2], bl[3]);
            }
        }
        __syncthreads();
    }

    const int g = lane >> 2;
    const int s0 = loc0 + w4 * 16 + g;
    const int s1 = s0 + 8;

    if (mt == 0) {              // ---- Q: fp32 ----
        float* O0 = g_Q + (((size_t)bb * NH + h) * NS + s0) * ND;
        float* O1 = g_Q + (((size_t)bb * NH + h) * NS + s1) * ND;
        #pragma unroll
        for (int j = 0; j < 8; j++) {
            int d = j * 8 + 2 * l4;
            float bx = bq[n0 + d], by = bq[n0 + d + 1];
            float2 v0 = { acc[j][0] + bx, acc[j][1] + by };
            float2 v1 = { acc[j][2] + bx, acc[j][3] + by };
            *(float2*)(O0 + d) = v0;
            *(float2*)(O1 + d) = v1;
        }
    } else if (mt == 1) {       // ---- K: fp16 ----
        size_t o0 = (((size_t)bb * NH + h) * NS + s0) * ND;
        size_t o1 = (((size_t)bb * NH + h) * NS + s1) * ND;
        #pragma unroll
        for (int j = 0; j < 8; j++) {
            int d = j * 8 + 2 * l4;
            float bx = bk[n0 + d], by = bk[n0 + d + 1];
            *(uint32_t*)(g_Kf + o0 + d) = pack_h2(acc[j][0] + bx, acc[j][1] + by);
            *(uint32_t*)(g_Kf + o1 + d) = pack_h2(acc[j][2] + bx, acc[j][3] + by);
        }
    } else {                    // ---- V: transpose via smem, fp16 [b,h,d,i] ----
        #define VPAD 68
        float* Vb = (float*)smb;
        #pragma unroll
        for (int j = 0; j < 8; j++) {
            int d = j * 8 + 2 * l4;
            float bx = bv[n0 + d], by = bv[n0 + d + 1];
            int sr0 = w4 * 16 + g, sr1 = sr0 + 8;
            Vb[(d    ) * VPAD + sr0] = acc[j][0] + bx;
            Vb[(d + 1) * VPAD + sr0] = acc[j][1] + by;
            Vb[(d    ) * VPAD + sr1] = acc[j][2] + bx;
            Vb[(d + 1) * VPAD + sr1] = acc[j][3] + by;
        }
        __syncthreads();
        #pragma unroll
        for (int it = 0; it < 8; it++) {
            int idx = tid + it * 128;
            int d = idx >> 4, c4 = (idx & 15) * 4;
            int s = loc0 + c4;
            size_t o = (((size_t)bb * NH + h) * ND + d) * NS + s;
            uint32_t hw[2] = { pack_h2(Vb[d * VPAD + c4],     Vb[d * VPAD + c4 + 1]),
                               pack_h2(Vb[d * VPAD + c4 + 2], Vb[d * VPAD + c4 + 3]) };
            *(uint2*)(g_Vf + o) = *(uint2*)hw;
        }
    }
}

// ---------------------------------------------------------------------------
// Kernel 2: flash attention, q-tile 64, 2 warpgroups split over K-tiles.
// ---------------------------------------------------------------------------
__global__ __launch_bounds__(256, 2) void attn_mma(
    const float* __restrict__ explore,
    const float* __restrict__ exploit)
{
    __shared__ __align__(16) __half Ks[2][64*KPAD];
    __shared__ __align__(16) __half Vs[2][64*KPAD];
    __shared__ float pens[2][64];

    const int tid  = threadIdx.x;
    const int w    = tid >> 5;
    const int wg   = w >> 2;
    const int w4   = w & 3;
    const int wtid = tid & 127;
    const int lane = tid & 31;
    const int g    = lane >> 2;
    const int l4   = lane & 3;
    const int matl = lane >> 3;
    const int rowl = lane & 7;
    const int q0   = blockIdx.x * 64;
    const int h    = blockIdx.y, b = blockIdx.z;

    const int cnt = g_cnt[b];
    if (q0 >= cnt) return;
    const int* idxp = g_idx + b * NS;
    const int NT = (cnt + 63) >> 6;

    const size_t base = ((size_t)b * NH + h) * NS * ND;
    const float* Qp = g_Q + base;
    const __half* Kp = g_Kf + base;
    const __half* Vp = g_Vf + base;

    const int r0 = w4 * 16 + g;
    const int r1 = r0 + 8;
    const int cq0 = q0 + r0, cq1 = q0 + r1;
    const int so0 = idxp[cq0], so1 = idxp[cq1];
    float rs0, rs1;
    {
        float t0 = 1.0f + 0.5f * explore[b * NS + so0] - 0.5f * exploit[b * NS + so0];
        t0 = fminf(fmaxf(t0, 0.5f), 2.0f);
        rs0 = 0.125f / t0;
        float t1 = 1.0f + 0.5f * explore[b * NS + so1] - 0.5f * exploit[b * NS + so1];
        t1 = fminf(fmaxf(t1, 0.5f), 2.0f);
        rs1 = 0.125f / t1;
    }

    uint32_t qf[4][4];
    #pragma unroll
    for (int kc = 0; kc < 4; kc++) {
        int d0 = kc * 16 + l4 * 2;
        const float2 a00 = *(const float2*)(Qp + (size_t)cq0 * ND + d0);
        const float2 a10 = *(const float2*)(Qp + (size_t)cq1 * ND + d0);
        const float2 a01 = *(const float2*)(Qp + (size_t)cq0 * ND + d0 + 8);
        const float2 a11 = *(const float2*)(Qp + (size_t)cq1 * ND + d0 + 8);
        qf[kc][0] = pack_h2(a00.x * rs0, a00.y * rs0);
        qf[kc][1] = pack_h2(a10.x * rs1, a10.y * rs1);
        qf[kc][2] = pack_h2(a01.x * rs0, a01.y * rs0);
        qf[kc][3] = pack_h2(a11.x * rs1, a11.y * rs1);
    }

    float oacc[8][4];
    #pragma unroll
    for (int j = 0; j < 8; j++)
        #pragma unroll
        for (int c = 0; c < 4; c++) oacc[j][c] = 0.f;
    float lsum0 = 0.f, lsum1 = 0.f;

    __half* Ksw = Ks[wg];
    __half* Vsw = Vs[wg];
    const int b_row = (matl >> 1) * 8 + rowl;
    const int b_kh  = (matl & 1) * 8;

    for (int kt = wg; kt < NT; kt += 2) {
        const int kk0 = kt * 64;

        #pragma unroll
        for (int it = 0; it < 4; it++) {
            int idx = wtid + it * 128;
            int r = idx >> 3, c8 = (idx & 7) * 8;
            *(uint4*)(Ksw + r * KPAD + c8) = *(const uint4*)(Kp + (size_t)(kk0 + r) * ND + c8);
            *(uint4*)(Vsw + r * KPAD + c8) = *(const uint4*)(Vp + (size_t)r * NS + kk0 + c8);
        }
        if (wtid < 64) pens[wg][wtid] = (kk0 + wtid < cnt) ? -11.0f : -1e30f;
        asm volatile("bar.sync %0, %1;" :: "r"(wg + 1), "r"(128) : "memory");

        float sacc[8][4];
        #pragma unroll
        for (int j = 0; j < 8; j++)
            #pragma unroll
            for (int c = 0; c < 4; c++) sacc[j][c] = 0.f;

        #pragma unroll
        for (int kc = 0; kc < 4; kc++) {
            #pragma unroll
            for (int jp = 0; jp < 4; jp++) {
                uint32_t kb[4];
                ldsm4(kb, Ksw + (jp * 16 + b_row) * KPAD + kc * 16 + b_kh);
                mma16816h(sacc[2*jp],   qf[kc], kb[0], kb[1]);
                mma16816h(sacc[2*jp+1], qf[kc], kb[2], kb[3]);
            }
        }

        uint32_t ps[8][2];
        #pragma unroll
        for (int j = 0; j < 8; j++) {
            float2 pen2 = *(const float2*)(&pens[wg][j * 8 + l4 * 2]);
            float p0 = __expf(sacc[j][0] + pen2.x);
            float p1 = __expf(sacc[j][1] + pen2.y);
            float p2 = __expf(sacc[j][2] + pen2.x);
            float p3 = __expf(sacc[j][3] + pen2.y);
            lsum0 += p0 + p1;
            lsum1 += p2 + p3;
            ps[j][0] = pack_h2(p0, p1);
            ps[j][1] = pack_h2(p2, p3);
        }

        #pragma unroll
        for (int kc = 0; kc < 4; kc++) {
            uint32_t Af[4] = { ps[2*kc][0], ps[2*kc][1], ps[2*kc+1][0], ps[2*kc+1][1] };
            #pragma unroll
            for (int jp = 0; jp < 4; jp++) {
                uint32_t vb[4];
                ldsm4(vb, Vsw + (jp * 16 + b_row) * KPAD + kc * 16 + b_kh);
                mma16816h(oacc[2*jp],   Af, vb[0], vb[1]);
                mma16816h(oacc[2*jp+1], Af, vb[2], vb[3]);
            }
        }
        asm volatile("bar.sync %0, %1;" :: "r"(wg + 1), "r"(128) : "memory");
    }

    lsum0 += __shfl_xor_sync(0xffffffffu, lsum0, 1);
    lsum0 += __shfl_xor_sync(0xffffffffu, lsum0, 2);
    lsum1 += __shfl_xor_sync(0xffffffffu, lsum1, 1);
    lsum1 += __shfl_xor_sync(0xffffffffu, lsum1, 2);

    __syncthreads();
    float* Ob = (float*)&Ks[0][0];
    float* Lb = Ob + 64 * 66;
    if (wg == 1) {
        #pragma unroll
        for (int j = 0; j < 8; j++) {
            int col = j * 8 + 2 * l4;
            Ob[r0 * 66 + col]     = oacc[j][0];
            Ob[r0 * 66 + col + 1] = oacc[j][1];
            Ob[r1 * 66 + col]     = oacc[j][2];
            Ob[r1 * 66 + col + 1] = oacc[j][3];
        }
        if (l4 == 0) { Lb[r0] = lsum0; Lb[r1] = lsum1; }
    }
    __syncthreads();
    if (wg == 0) {
        lsum0 += Lb[r0];
        lsum1 += Lb[r1];
        float inv0 = (lsum0 > 0.f) ? 1.f / lsum0 : 0.f;
        float inv1 = (lsum1 > 0.f) ? 1.f / lsum1 : 0.f;
        if (cq0 < cnt) {
            size_t o0 = base + (size_t)cq0 * ND;
            #pragma unroll
            for (int j = 0; j < 8; j++) {
                int col = j * 8 + 2 * l4;
                float v0 = (oacc[j][0] + Ob[r0 * 66 + col])     * inv0;
                float v1 = (oacc[j][1] + Ob[r0 * 66 + col + 1]) * inv0;
                float h0,l0,h1,l1;
                split_hi_lo(v0, h0, l0); split_hi_lo(v1, h1, l1);
                *(uint32_t*)(g_AOh + o0 + col) = pack_bf16x2(h0, h1);
                *(uint32_t*)(g_AOl + o0 + col) = pack_bf16x2(l0, l1);
            }
        }
        if (cq1 < cnt) {
            size_t o1 = base + (size_t)cq1 * ND;
            #pragma unroll
            for (int j = 0; j < 8; j++) {
                int col = j * 8 + 2 * l4;
                float v0 = (oacc[j][2] + Ob[r1 * 66 + col])     * inv1;
                float v1 = (oacc[j][3] + Ob[r1 * 66 + col + 1]) * inv1;
                float h0,l0,h1,l1;
                split_hi_lo(v0, h0, l0); split_hi_lo(v1, h1, l1);
                *(uint32_t*)(g_AOh + o1 + col) = pack_bf16x2(h0, h1);
                *(uint32_t*)(g_AOl + o1 + col) = pack_bf16x2(l0, l1);
            }
        }
    }
}

// ---------------------------------------------------------------------------
// Kernel 3: output projection, cp.async 2-stage pipeline, compacted rows.
// ---------------------------------------------------------------------------
#define OP_SMEM_BF16 (2 * 4 * S1)    // 73728 B

__global__ __launch_bounds__(128, 3) void out_proj_mma(
    const float* __restrict__ bo,
    float* __restrict__ out)
{
    extern __shared__ __nv_bfloat16 smb[];

    const int tid  = threadIdx.x;
    const int w4   = tid >> 5;
    const int lane = tid & 31;
    const int l4   = lane & 3;
    const int matl = lane >> 3;
    const int rowl = lane & 7;
    const int m0   = blockIdx.x * 64;
    const int n0   = blockIdx.y * 64;

    const int bb   = m0 >> 11;
    const int loc0 = m0 & (NS - 1);
    const int cnt  = g_cnt[bb];
    if (loc0 >= cnt) return;
    const int* idxp = g_idx + bb * NS;

    const __nv_bfloat16* Wthg = g_Wth + (size_t)3 * NE * NE + (size_t)n0 * NE;
    const __nv_bfloat16* Wtlg = g_Wtl + (size_t)3 * NE * NE + (size_t)n0 * NE;

    float acc[8][4];
    #pragma unroll
    for (int j = 0; j < 8; j++)
        #pragma unroll
        for (int c = 0; c < 4; c++) acc[j][c] = 0.f;

    const int a_off = (w4 * 16 + (matl & 1) * 8 + rowl) * KPAD + (matl >> 1) * 8;
    const int b_row = (matl >> 1) * 8 + rowl;
    const int b_kh  = (matl & 1) * 8;
    const int ldr = tid >> 3, ldc = (tid & 7) * 8;

    auto load_stage = [&](int s, int k0) {
        __nv_bfloat16* sb = smb + s * 4 * S1;
        const int hh = k0 >> 6;
        const __nv_bfloat16* Ah = g_AOh + (((size_t)bb * NH + hh) * NS + loc0) * ND;
        const __nv_bfloat16* Al = g_AOl + (((size_t)bb * NH + hh) * NS + loc0) * ND;
        #pragma unroll
        for (int it = 0; it < 4; it++) {
            int r = ldr + it * 16;
            cpa16(sb +        r * KPAD + ldc, Ah + (size_t)r * ND + ldc);
            cpa16(sb + S1   + r * KPAD + ldc, Al + (size_t)r * ND + ldc);
            cpa16(sb + 2*S1 + r * KPAD + ldc, Wthg + (size_t)r * NE + k0 + ldc);
            cpa16(sb + 3*S1 + r * KPAD + ldc, Wtlg + (size_t)r * NE + k0 + ldc);
        }
        CP_COMMIT();
    };

    load_stage(0, 0);
    for (int i = 0; i < 4; i++) {
        if (i < 3) { load_stage((i + 1) & 1, (i + 1) * 64); CP_WAIT1(); }
        else       { CP_WAIT0(); }
        __syncthreads();

        const __nv_bfloat16* sb  = smb + (i & 1) * 4 * S1;
        const __nv_bfloat16* Xh  = sb;
        const __nv_bfloat16* Xl  = sb + S1;
        const __nv_bfloat16* Wth = sb + 2 * S1;
        const __nv_bfloat16* Wtl = sb + 3 * S1;

        #pragma unroll
        for (int kc = 0; kc < 4; kc++) {
            uint32_t ah[4], al[4];
            ldsm4(ah, Xh + a_off + kc * 16);
            ldsm4(al, Xl + a_off + kc * 16);
            #pragma unroll
            for (int jp = 0; jp < 4; jp++) {
                int boff = (jp * 16 + b_row) * KPAD + kc * 16 + b_kh;
                uint32_t bh[4], bl[4];
                ldsm4(bh, Wth + boff);
                ldsm4(bl, Wtl + boff);
                mma16816(acc[2*jp],   ah, bh[0], bh[1]);
                mma16816(acc[2*jp],   al, bh[0], bh[1]);
                mma16816(acc[2*jp],   ah, bl[0], bl[1]);
                mma16816(acc[2*jp+1], ah, bh[2], bh[3]);
                mma16816(acc[2*jp+1], al, bh[2], bh[3]);
                mma16816(acc[2*jp+1], ah, bl[2], bl[3]);
            }
        }
        __syncthreads();
    }

    const int g = lane >> 2;
    const int lr0 = loc0 + w4 * 16 + g;
    const int lr1 = lr0 + 8;
    if (lr0 < cnt) {
        int row = bb * NS + idxp[lr0];
        #pragma unroll
        for (int j = 0; j < 8; j++) {
            int d = j * 8 + 2 * l4;
            float2 v = { acc[j][0] + bo[n0 + d], acc[j][1] + bo[n0 + d + 1] };
            *(float2*)(out + (size_t)row * NE + n0 + d) = v;
        }
    }
    if (lr1 < cnt) {
        int row = bb * NS + idxp[lr1];
        #pragma unroll
        for (int j = 0; j < 8; j++) {
            int d = j * 8 + 2 * l4;
            float2 v = { acc[j][2] + bo[n0 + d], acc[j][3] + bo[n0 + d + 1] };
            *(float2*)(out + (size_t)row * NE + n0 + d) = v;
        }
    }
}

// ---------------------------------------------------------------------------
extern "C" void kernel_launch(void* const* d_in, const int* in_sizes, int n_in,
                              void* d_out, int out_size)
{
    const float* his     = (const float*)d_in[0];
    const int*   mask    = (const int*)d_in[1];
    const float* explore = (const float*)d_in[2];
    const float* exploit = (const float*)d_in[3];
    const float* Wq = (const float*)d_in[4];
    const float* bq = (const float*)d_in[5];
    const float* Wk = (const float*)d_in[6];
    const float* bk = (const float*)d_in[7];
    const float* Wv = (const float*)d_in[8];
    const float* bv = (const float*)d_in[9];
    const float* Wo = (const float*)d_in[10];
    const float* bo = (const float*)d_in[11];
    float* out = (float*)d_out;

    const int qkv_smem = QKV_SMEM_BF16 * 2;     // 73728 B
    const int op_smem  = OP_SMEM_BF16 * 2;      // 73728 B
    static cudaStream_t s2 = nullptr, s3 = nullptr;
    static cudaEvent_t ev_root = nullptr, ev_w = nullptr, ev_z = nullptr;
    if (s2 == nullptr) {
        cudaFuncSetAttribute(qkv_mma, cudaFuncAttributeMaxDynamicSharedMemorySize, qkv_smem);
        cudaFuncSetAttribute(out_proj_mma, cudaFuncAttributeMaxDynamicSharedMemorySize, op_smem);
        cudaStreamCreateWithFlags(&s2, cudaStreamNonBlocking);
        cudaStreamCreateWithFlags(&s3, cudaStreamNonBlocking);
        cudaEventCreateWithFlags(&ev_root, cudaEventDisableTiming);
        cudaEventCreateWithFlags(&ev_w, cudaEventDisableTiming);
        cudaEventCreateWithFlags(&ev_z, cudaEventDisableTiming);
    }

    // fork: prep_w on s2, zero_masked on s3, build_idx + prep_x on main
    cudaEventRecord(ev_root, 0);
    cudaStreamWaitEvent(s2, ev_root, 0);
    cudaStreamWaitEvent(s3, ev_root, 0);
    prep_w<<<dim3(4, 4, 4), 256, 0, s2>>>(Wq, Wk, Wv, Wo);
    zero_masked<<<NB * NS / 4, 256, 0, s3>>>(mask, out);
    build_idx<<<NB, 1024>>>(mask);
    prep_x<<<NB * NS / 16, 256>>>(his);

    // join prep_w before qkv (needs g_Wth/g_Wtl)
    cudaEventRecord(ev_w, s2);
    cudaStreamWaitEvent(0, ev_w, 0);
    qkv_mma<<<dim3(NB * NS / 64, NH, 3), 128, qkv_smem>>>(bq, bk, bv);
    attn_mma<<<dim3(NS / 64, NH, NB), 256>>>(explore, exploit);

    // join zero_masked before out_proj (both write `out`, disjoint rows)
    cudaEventRecord(ev_z, s3);
    cudaStreamWaitEvent(0, ev_z, 0);
    out_proj_mma<<<dim3(NB * NS / 64, 4), 128, op_smem>>>(bo, out);
}

// round 15
// speedup vs baseline: 1.1156x; 1.0542x over previous
#include <cuda_runtime.h>
#include <cuda_bf16.h>
#include <cuda_fp16.h>
#include <cstdint>
#include <math.h>

#define NB 4
#define NS 2048
#define NE 256
#define NH 4
#define ND 64

// Scratch (allocation-free). All seq-indexed arrays in COMPACTED coordinates.
__device__ float g_Q[NB*NH*NS*ND];                                  // [b,h,i,d] fp32
__device__ __align__(16) __half g_Kf[NB*NH*NS*ND];                  // [b,h,i,d] fp16
__device__ __align__(16) __half g_Vf[NB*NH*ND*NS];                  // [b,h,d,i] fp16
__device__ __align__(16) __nv_bfloat16 g_AOh[NB*NH*NS*ND];          // [b,h,i,d]
__device__ __align__(16) __nv_bfloat16 g_AOl[NB*NH*NS*ND];
__device__ __align__(16) __nv_bfloat16 g_Wth[4*NE*NE];              // [mat][n][k]
__device__ __align__(16) __nv_bfloat16 g_Wtl[4*NE*NE];
__device__ __align__(16) __nv_bfloat16 g_Xh[NB*NS*NE];              // [b,i,k] pre-split X
__device__ __align__(16) __nv_bfloat16 g_Xl[NB*NS*NE];
__device__ int g_idx[NB*NS];     // [0..cnt) unmasked orig s; [cnt..NS) masked orig s
__device__ int g_cnt[NB];

__device__ __forceinline__ uint32_t pack_bf16x2(float a, float b) {
    __nv_bfloat162 t = __floats2bfloat162_rn(a, b);   // a -> low half
    return *(uint32_t*)&t;
}
__device__ __forceinline__ uint32_t pack_h2(float a, float b) {
    __half2 t = __floats2half2_rn(a, b);              // a -> low half
    return *(uint32_t*)&t;
}
__device__ __forceinline__ void split_hi_lo(float x, float& hi, float& lo) {
    __nv_bfloat16 h = __float2bfloat16_rn(x);
    hi = __bfloat162float(h);
    lo = x - hi;
}

// mma.sync m16n8k16 row.col (sm_80+ PTX, no arch suffix)
__device__ __forceinline__ void mma16816(float c[4], const uint32_t a[4],
                                         uint32_t b0, uint32_t b1) {
    asm volatile(
        "mma.sync.aligned.m16n8k16.row.col.f32.bf16.bf16.f32 "
        "{%0,%1,%2,%3}, {%4,%5,%6,%7}, {%8,%9}, {%0,%1,%2,%3};"
        : "+f"(c[0]), "+f"(c[1]), "+f"(c[2]), "+f"(c[3])
        : "r"(a[0]), "r"(a[1]), "r"(a[2]), "r"(a[3]), "r"(b0), "r"(b1));
}
__device__ __forceinline__ void mma16816h(float c[4], const uint32_t a[4],
                                          uint32_t b0, uint32_t b1) {
    asm volatile(
        "mma.sync.aligned.m16n8k16.row.col.f32.f16.f16.f32 "
        "{%0,%1,%2,%3}, {%4,%5,%6,%7}, {%8,%9}, {%0,%1,%2,%3};"
        : "+f"(c[0]), "+f"(c[1]), "+f"(c[2]), "+f"(c[3])
        : "r"(a[0]), "r"(a[1]), "r"(a[2]), "r"(a[3]), "r"(b0), "r"(b1));
}

// ldmatrix x4 (sm_75+)
__device__ __forceinline__ void ldsm4(uint32_t r[4], const void* p) {
    uint32_t a = (uint32_t)__cvta_generic_to_shared(p);
    asm volatile("ldmatrix.sync.aligned.m8n8.x4.shared.b16 {%0,%1,%2,%3}, [%4];"
                 : "=r"(r[0]), "=r"(r[1]), "=r"(r[2]), "=r"(r[3]) : "r"(a));
}

// cp.async 16B (sm_80+)
__device__ __forceinline__ void cpa16(void* dst, const void* src) {
    uint32_t d = (uint32_t)__cvta_generic_to_shared(dst);
    asm volatile("cp.async.cg.shared.global [%0], [%1], 16;" :: "r"(d), "l"(src));
}
#define CP_COMMIT() asm volatile("cp.async.commit_group;")
#define CP_WAIT1()  asm volatile("cp.async.wait_group 1;")
#define CP_WAIT0()  asm volatile("cp.async.wait_group 0;")

#define KPAD 72   // 16-bit row stride; 36-word stride -> conflict-free ldmatrix rows
#define S1 (64*KPAD)

// ---------------------------------------------------------------------------
// Kernel A: per-batch compaction index. Unmasked -> [0,cnt), masked -> [cnt,NS).
// ---------------------------------------------------------------------------
__global__ __launch_bounds__(1024) void build_idx(const int* __restrict__ mask)
{
    __shared__ int scan[1024];
    const int b = blockIdx.x;
    const int tid = threadIdx.x;
    const int s0 = 2 * tid, s1 = 2 * tid + 1;
    const int m0 = (mask[b * NS + s0] == 0) ? 1 : 0;
    const int m1 = (mask[b * NS + s1] == 0) ? 1 : 0;
    scan[tid] = m0 + m1;
    __syncthreads();
    #pragma unroll
    for (int off = 1; off < 1024; off <<= 1) {
        int v = (tid >= off) ? scan[tid - off] : 0;
        __syncthreads();
        scan[tid] += v;
        __syncthreads();
    }
    const int excl = scan[tid] - m0 - m1;      // unmasked before s0
    const int total = scan[1023];
    if (m0) g_idx[b * NS + excl] = s0;
    else    g_idx[b * NS + total + (s0 - excl)] = s0;
    if (m1) g_idx[b * NS + excl + m0] = s1;
    else    g_idx[b * NS + total + (s1 - excl - m0)] = s1;
    if (tid == 0) g_cnt[b] = total;
}

// ---------------------------------------------------------------------------
// Kernel A2: fused prep_x (blocks 0..511) + prep_w (blocks 512..575).
// ---------------------------------------------------------------------------
__global__ __launch_bounds__(256) void prep_xw(
    const float* __restrict__ X,
    const float* __restrict__ Wq, const float* __restrict__ Wk,
    const float* __restrict__ Wv, const float* __restrict__ Wo)
{
    __shared__ float t[64][65];
    const int tid = threadIdx.x;

    if (blockIdx.x < 512) {
        // ---- prep_x: 16 compacted rows/block ----
        const int m0 = blockIdx.x * 16;
        const int bb = m0 >> 11, loc0 = m0 & (NS - 1);
        const int cnt = g_cnt[bb];
        if (loc0 >= cnt) return;
        const int* idxp = g_idx + bb * NS;

        #pragma unroll
        for (int it = 0; it < 4; it++) {
            int idx = tid + it * 256;
            int r = idx >> 6, c4 = (idx & 63) * 4;
            int src = idxp[loc0 + r];
            float4 v = *(const float4*)(X + ((size_t)bb * NS + src) * NE + c4);
            float h0,l0,h1,l1,h2,l2,h3,l3;
            split_hi_lo(v.x,h0,l0); split_hi_lo(v.y,h1,l1);
            split_hi_lo(v.z,h2,l2); split_hi_lo(v.w,h3,l3);
            size_t o = ((size_t)bb * NS + loc0 + r) * NE + c4;
            uint32_t hw[2] = { pack_bf16x2(h0,h1), pack_bf16x2(h2,h3) };
            uint32_t lw[2] = { pack_bf16x2(l0,l1), pack_bf16x2(l2,l3) };
            *(uint2*)(g_Xh + o) = *(uint2*)hw;
            *(uint2*)(g_Xl + o) = *(uint2*)lw;
        }
    } else {
        // ---- prep_w: one 64x64 tile per block ----
        const int bidx = blockIdx.x - 512;      // 0..63
        const int mt = bidx >> 4;
        const int k0 = ((bidx >> 2) & 3) * 64, n0 = (bidx & 3) * 64;
        const float* Ws[4] = { Wq, Wk, Wv, Wo };
        const float* W = Ws[mt];

        #pragma unroll
        for (int it = 0; it < 16; it++) {
            int idx = tid + it * 256;
            int kk = idx >> 6, nn = idx & 63;
            t[kk][nn] = W[(k0 + kk) * NE + n0 + nn];
        }
        __syncthreads();

        #pragma unroll
        for (int it = 0; it < 2; it++) {
            int idx = tid + it * 256;
            int n = idx >> 3, c8 = (idx & 7) * 8;
            uint32_t hw[4], lw[4];
            #pragma unroll
            for (int p = 0; p < 4; p++) {
                float hi0, lo0, hi1, lo1;
                split_hi_lo(t[c8 + 2*p][n],     hi0, lo0);
                split_hi_lo(t[c8 + 2*p + 1][n], hi1, lo1);
                hw[p] = pack_bf16x2(hi0, hi1);
                lw[p] = pack_bf16x2(lo0, lo1);
            }
            size_t o = (size_t)mt * NE * NE + (size_t)(n0 + n) * NE + k0 + c8;
            *(uint4*)(g_Wth + o) = *(uint4*)hw;
            *(uint4*)(g_Wtl + o) = *(uint4*)lw;
        }
    }
}

// ---------------------------------------------------------------------------
// Kernel 1: QKV projection, one weight matrix per blockIdx.z.
// cp.async 2-stage pipeline, ldmatrix fragments.
// ---------------------------------------------------------------------------
#define QKV_SMEM_BF16 (2 * 4 * S1)    // 73728 B

__global__ __launch_bounds__(128, 3) void qkv_mma(
    const float* __restrict__ bq, const float* __restrict__ bk,
    const float* __restrict__ bv)
{
    extern __shared__ __nv_bfloat16 smb[];

    const int tid  = threadIdx.x;
    const int w4   = tid >> 5;
    const int lane = tid & 31;
    const int l4   = lane & 3;
    const int matl = lane >> 3;
    const int rowl = lane & 7;
    const int m0   = blockIdx.x * 64;
    const int h    = blockIdx.y;
    const int mt   = blockIdx.z;
    const int n0   = h * 64;

    const int bb   = m0 >> 11;
    const int loc0 = m0 & (NS - 1);
    const int cnt  = g_cnt[bb];
    if (loc0 >= cnt) return;

    const __nv_bfloat16* Xhg = g_Xh + ((size_t)bb * NS + loc0) * NE;
    const __nv_bfloat16* Xlg = g_Xl + ((size_t)bb * NS + loc0) * NE;
    const __nv_bfloat16* Wthg = g_Wth + (size_t)mt * NE * NE + (size_t)n0 * NE;
    const __nv_bfloat16* Wtlg = g_Wtl + (size_t)mt * NE * NE + (size_t)n0 * NE;

    float acc[8][4];
    #pragma unroll
    for (int j = 0; j < 8; j++)
        #pragma unroll
        for (int c = 0; c < 4; c++) acc[j][c] = 0.f;

    const int a_off = (w4 * 16 + (matl & 1) * 8 + rowl) * KPAD + (matl >> 1) * 8;
    const int b_row = (matl >> 1) * 8 + rowl;
    const int b_kh  = (matl & 1) * 8;

    const int ldr = tid >> 3, ldc = (tid & 7) * 8;

    auto load_stage = [&](int s, int k0) {
        __nv_bfloat16* sb = smb + s * 4 * S1;
        #pragma unroll
        for (int it = 0; it < 4; it++) {
            int r = ldr + it * 16;
            cpa16(sb +        r * KPAD + ldc, Xhg  + (size_t)r * NE + k0 + ldc);
            cpa16(sb + S1   + r * KPAD + ldc, Xlg  + (size_t)r * NE + k0 + ldc);
            cpa16(sb + 2*S1 + r * KPAD + ldc, Wthg + (size_t)r * NE + k0 + ldc);
            cpa16(sb + 3*S1 + r * KPAD + ldc, Wtlg + (size_t)r * NE + k0 + ldc);
        }
        CP_COMMIT();
    };

    load_stage(0, 0);
    for (int i = 0; i < 4; i++) {
        if (i < 3) { load_stage((i + 1) & 1, (i + 1) * 64); CP_WAIT1(); }
        else       { CP_WAIT0(); }
        __syncthreads();

        const __nv_bfloat16* sb  = smb + (i & 1) * 4 * S1;
        const __nv_bfloat16* Xh  = sb;
        const __nv_bfloat16* Xl  = sb + S1;
        const __nv_bfloat16* Wth = sb + 2 * S1;
        const __nv_bfloat16* Wtl = sb + 3 * S1;

        #pragma unroll
        for (int kc = 0; kc < 4; kc++) {
            uint32_t ah[4], al[4];
            ldsm4(ah, Xh + a_off + kc * 16);
            ldsm4(al, Xl + a_off + kc * 16);
            #pragma unroll
            for (int jp = 0; jp < 4; jp++) {
                int boff = (jp * 16 + b_row) * KPAD + kc * 16 + b_kh;
                uint32_t bh[4], bl[4];
                ldsm4(bh, Wth + boff);
                ldsm4(bl, Wtl + boff);
                mma16816(acc[2*jp],   ah, bh[0], bh[1]);
                mma16816(acc[2*jp],   al, bh[0], bh[1]);
                mma16816(acc[2*jp],   ah, bl[0], bl[1]);
                mma16816(acc[2*jp+1], ah, bh[2], bh[3]);
                mma16816(acc[2*jp+1], al, bh[2], bh[3]);
                mma16816(acc[2*jp+1], ah, bl[2], bl[3]);
            }
        }
        __syncthreads();
    }

    const int g = lane >> 2;
    const int s0 = loc0 + w4 * 16 + g;
    const int s1 = s0 + 8;

    if (mt == 0) {              // ---- Q: fp32 ----
        float* O0 = g_Q + (((size_t)bb * NH + h) * NS + s0) * ND;
        float* O1 = g_Q + (((size_t)bb * NH + h) * NS + s1) * ND;
        #pragma unroll
        for (int j = 0; j < 8; j++) {
            int d = j * 8 + 2 * l4;
            float bx = bq[n0 + d], by = bq[n0 + d + 1];
            float2 v0 = { acc[j][0] + bx, acc[j][1] + by };
            float2 v1 = { acc[j][2] + bx, acc[j][3] + by };
            *(float2*)(O0 + d) = v0;
            *(float2*)(O1 + d) = v1;
        }
    } else if (mt == 1) {       // ---- K: fp16 ----
        size_t o0 = (((size_t)bb * NH + h) * NS + s0) * ND;
        size_t o1 = (((size_t)bb * NH + h) * NS + s1) * ND;
        #pragma unroll
        for (int j = 0; j < 8; j++) {
            int d = j * 8 + 2 * l4;
            float bx = bk[n0 + d], by = bk[n0 + d + 1];
            *(uint32_t*)(g_Kf + o0 + d) = pack_h2(acc[j][0] + bx, acc[j][1] + by);
            *(uint32_t*)(g_Kf + o1 + d) = pack_h2(acc[j][2] + bx, acc[j][3] + by);
        }
    } else {                    // ---- V: transpose via smem, fp16 [b,h,d,i] ----
        #define VPAD 68
        float* Vb = (float*)smb;
        __syncthreads();
        #pragma unroll
        for (int j = 0; j < 8; j++) {
            int d = j * 8 + 2 * l4;
            float bx = bv[n0 + d], by = bv[n0 + d + 1];
            int sr0 = w4 * 16 + g, sr1 = sr0 + 8;
            Vb[(d    ) * VPAD + sr0] = acc[j][0] + bx;
            Vb[(d + 1) * VPAD + sr0] = acc[j][1] + by;
            Vb[(d    ) * VPAD + sr1] = acc[j][2] + bx;
            Vb[(d + 1) * VPAD + sr1] = acc[j][3] + by;
        }
        __syncthreads();
        #pragma unroll
        for (int it = 0; it < 8; it++) {
            int idx = tid + it * 128;
            int d = idx >> 4, c4 = (idx & 15) * 4;
            int s = loc0 + c4;
            size_t o = (((size_t)bb * NH + h) * ND + d) * NS + s;
            uint32_t hw[2] = { pack_h2(Vb[d * VPAD + c4],     Vb[d * VPAD + c4 + 1]),
                               pack_h2(Vb[d * VPAD + c4 + 2], Vb[d * VPAD + c4 + 3]) };
            *(uint2*)(g_Vf + o) = *(uint2*)hw;
        }
    }
}

// ---------------------------------------------------------------------------
// Kernel 2: flash attention, q-tile 64, 2 warpgroups split over K-tiles.
// ---------------------------------------------------------------------------
__global__ __launch_bounds__(256, 2) void attn_mma(
    const float* __restrict__ explore,
    const float* __restrict__ exploit)
{
    __shared__ __align__(16) __half Ks[2][64*KPAD];
    __shared__ __align__(16) __half Vs[2][64*KPAD];
    __shared__ float pens[2][64];

    const int tid  = threadIdx.x;
    const int w    = tid >> 5;
    const int wg   = w >> 2;
    const int w4   = w & 3;
    const int wtid = tid & 127;
    const int lane = tid & 31;
    const int g    = lane >> 2;
    const int l4   = lane & 3;
    const int matl = lane >> 3;
    const int rowl = lane & 7;
    const int q0   = blockIdx.x * 64;
    const int h    = blockIdx.y, b = blockIdx.z;

    const int cnt = g_cnt[b];
    if (q0 >= cnt) return;
    const int* idxp = g_idx + b * NS;
    const int NT = (cnt + 63) >> 6;

    const size_t base = ((size_t)b * NH + h) * NS * ND;
    const float* Qp = g_Q + base;
    const __half* Kp = g_Kf + base;
    const __half* Vp = g_Vf + base;

    const int r0 = w4 * 16 + g;
    const int r1 = r0 + 8;
    const int cq0 = q0 + r0, cq1 = q0 + r1;
    const int so0 = idxp[cq0], so1 = idxp[cq1];
    float rs0, rs1;
    {
        float t0 = 1.0f + 0.5f * explore[b * NS + so0] - 0.5f * exploit[b * NS + so0];
        t0 = fminf(fmaxf(t0, 0.5f), 2.0f);
        rs0 = 0.125f / t0;
        float t1 = 1.0f + 0.5f * explore[b * NS + so1] - 0.5f * exploit[b * NS + so1];
        t1 = fminf(fmaxf(t1, 0.5f), 2.0f);
        rs1 = 0.125f / t1;
    }

    uint32_t qf[4][4];
    #pragma unroll
    for (int kc = 0; kc < 4; kc++) {
        int d0 = kc * 16 + l4 * 2;
        const float2 a00 = *(const float2*)(Qp + (size_t)cq0 * ND + d0);
        const float2 a10 = *(const float2*)(Qp + (size_t)cq1 * ND + d0);
        const float2 a01 = *(const float2*)(Qp + (size_t)cq0 * ND + d0 + 8);
        const float2 a11 = *(const float2*)(Qp + (size_t)cq1 * ND + d0 + 8);
        qf[kc][0] = pack_h2(a00.x * rs0, a00.y * rs0);
        qf[kc][1] = pack_h2(a10.x * rs1, a10.y * rs1);
        qf[kc][2] = pack_h2(a01.x * rs0, a01.y * rs0);
        qf[kc][3] = pack_h2(a11.x * rs1, a11.y * rs1);
    }

    float oacc[8][4];
    #pragma unroll
    for (int j = 0; j < 8; j++)
        #pragma unroll
        for (int c = 0; c < 4; c++) oacc[j][c] = 0.f;
    float lsum0 = 0.f, lsum1 = 0.f;

    __half* Ksw = Ks[wg];
    __half* Vsw = Vs[wg];
    const int b_row = (matl >> 1) * 8 + rowl;
    const int b_kh  = (matl & 1) * 8;

    for (int kt = wg; kt < NT; kt += 2) {
        const int kk0 = kt * 64;

        #pragma unroll
        for (int it = 0; it < 4; it++) {
            int idx = wtid + it * 128;
            int r = idx >> 3, c8 = (idx & 7) * 8;
            *(uint4*)(Ksw + r * KPAD + c8) = *(const uint4*)(Kp + (size_t)(kk0 + r) * ND + c8);
            *(uint4*)(Vsw + r * KPAD + c8) = *(const uint4*)(Vp + (size_t)r * NS + kk0 + c8);
        }
        if (wtid < 64) pens[wg][wtid] = (kk0 + wtid < cnt) ? -11.0f : -1e30f;
        asm volatile("bar.sync %0, %1;" :: "r"(wg + 1), "r"(128) : "memory");

        float sacc[8][4];
        #pragma unroll
        for (int j = 0; j < 8; j++)
            #pragma unroll
            for (int c = 0; c < 4; c++) sacc[j][c] = 0.f;

        #pragma unroll
        for (int kc = 0; kc < 4; kc++) {
            #pragma unroll
            for (int jp = 0; jp < 4; jp++) {
                uint32_t kb[4];
                ldsm4(kb, Ksw + (jp * 16 + b_row) * KPAD + kc * 16 + b_kh);
                mma16816h(sacc[2*jp],   qf[kc], kb[0], kb[1]);
                mma16816h(sacc[2*jp+1], qf[kc], kb[2], kb[3]);
            }
        }

        uint32_t ps[8][2];
        #pragma unroll
        for (int j = 0; j < 8; j++) {
            float2 pen2 = *(const float2*)(&pens[wg][j * 8 + l4 * 2]);
            float p0 = __expf(sacc[j][0] + pen2.x);
            float p1 = __expf(sacc[j][1] + pen2.y);
            float p2 = __expf(sacc[j][2] + pen2.x);
            float p3 = __expf(sacc[j][3] + pen2.y);
            lsum0 += p0 + p1;
            lsum1 += p2 + p3;
            ps[j][0] = pack_h2(p0, p1);
            ps[j][1] = pack_h2(p2, p3);
        }

        #pragma unroll
        for (int kc = 0; kc < 4; kc++) {
            uint32_t Af[4] = { ps[2*kc][0], ps[2*kc][1], ps[2*kc+1][0], ps[2*kc+1][1] };
            #pragma unroll
            for (int jp = 0; jp < 4; jp++) {
                uint32_t vb[4];
                ldsm4(vb, Vsw + (jp * 16 + b_row) * KPAD + kc * 16 + b_kh);
                mma16816h(oacc[2*jp],   Af, vb[0], vb[1]);
                mma16816h(oacc[2*jp+1], Af, vb[2], vb[3]);
            }
        }
        asm volatile("bar.sync %0, %1;" :: "r"(wg + 1), "r"(128) : "memory");
    }

    lsum0 += __shfl_xor_sync(0xffffffffu, lsum0, 1);
    lsum0 += __shfl_xor_sync(0xffffffffu, lsum0, 2);
    lsum1 += __shfl_xor_sync(0xffffffffu, lsum1, 1);
    lsum1 += __shfl_xor_sync(0xffffffffu, lsum1, 2);

    __syncthreads();
    float* Ob = (float*)&Ks[0][0];
    float* Lb = Ob + 64 * 66;
    if (wg == 1) {
        #pragma unroll
        for (int j = 0; j < 8; j++) {
            int col = j * 8 + 2 * l4;
            Ob[r0 * 66 + col]     = oacc[j][0];
            Ob[r0 * 66 + col + 1] = oacc[j][1];
            Ob[r1 * 66 + col]     = oacc[j][2];
            Ob[r1 * 66 + col + 1] = oacc[j][3];
        }
        if (l4 == 0) { Lb[r0] = lsum0; Lb[r1] = lsum1; }
    }
    __syncthreads();
    if (wg == 0) {
        lsum0 += Lb[r0];
        lsum1 += Lb[r1];
        float inv0 = (lsum0 > 0.f) ? 1.f / lsum0 : 0.f;
        float inv1 = (lsum1 > 0.f) ? 1.f / lsum1 : 0.f;
        if (cq0 < cnt) {
            size_t o0 = base + (size_t)cq0 * ND;
            #pragma unroll
            for (int j = 0; j < 8; j++) {
                int col = j * 8 + 2 * l4;
                float v0 = (oacc[j][0] + Ob[r0 * 66 + col])     * inv0;
                float v1 = (oacc[j][1] + Ob[r0 * 66 + col + 1]) * inv0;
                float h0,l0,h1,l1;
                split_hi_lo(v0, h0, l0); split_hi_lo(v1, h1, l1);
                *(uint32_t*)(g_AOh + o0 + col) = pack_bf16x2(h0, h1);
                *(uint32_t*)(g_AOl + o0 + col) = pack_bf16x2(l0, l1);
            }
        }
        if (cq1 < cnt) {
            size_t o1 = base + (size_t)cq1 * ND;
            #pragma unroll
            for (int j = 0; j < 8; j++) {
                int col = j * 8 + 2 * l4;
                float v0 = (oacc[j][2] + Ob[r1 * 66 + col])     * inv1;
                float v1 = (oacc[j][3] + Ob[r1 * 66 + col + 1]) * inv1;
                float h0,l0,h1,l1;
                split_hi_lo(v0, h0, l0); split_hi_lo(v1, h1, l1);
                *(uint32_t*)(g_AOh + o1 + col) = pack_bf16x2(h0, h1);
                *(uint32_t*)(g_AOl + o1 + col) = pack_bf16x2(l0, l1);
            }
        }
    }
}

// ---------------------------------------------------------------------------
// Kernel 3: output projection + masked-row zeroing (tail/partial blocks).
// ---------------------------------------------------------------------------
#define OP_SMEM_BF16 (2 * 4 * S1)    // 73728 B

__global__ __launch_bounds__(128, 3) void out_proj_mma(
    const float* __restrict__ bo,
    float* __restrict__ out)
{
    extern __shared__ __nv_bfloat16 smb[];

    const int tid  = threadIdx.x;
    const int w4   = tid >> 5;
    const int lane = tid & 31;
    const int l4   = lane & 3;
    const int matl = lane >> 3;
    const int rowl = lane & 7;
    const int m0   = blockIdx.x * 64;
    const int n0   = blockIdx.y * 64;

    const int bb   = m0 >> 11;
    const int loc0 = m0 & (NS - 1);
    const int cnt  = g_cnt[bb];
    const int* idxp = g_idx + bb * NS;

    if (loc0 >= cnt) {
        // pure zero block: rows are masked originals (idx[cnt..NS))
        #pragma unroll
        for (int it = 0; it < 8; it++) {
            int idx = tid + it * 128;
            int r = idx >> 4, c4 = (idx & 15) * 4;
            int row = bb * NS + idxp[loc0 + r];
            float4 z = {0.f, 0.f, 0.f, 0.f};
            *(float4*)(out + (size_t)row * NE + n0 + c4) = z;
        }
        return;
    }

    const __nv_bfloat16* Wthg = g_Wth + (size_t)3 * NE * NE + (size_t)n0 * NE;
    const __nv_bfloat16* Wtlg = g_Wtl + (size_t)3 * NE * NE + (size_t)n0 * NE;

    float acc[8][4];
    #pragma unroll
    for (int j = 0; j < 8; j++)
        #pragma unroll
        for (int c = 0; c < 4; c++) acc[j][c] = 0.f;

    const int a_off = (w4 * 16 + (matl & 1) * 8 + rowl) * KPAD + (matl >> 1) * 8;
    const int b_row = (matl >> 1) * 8 + rowl;
    const int b_kh  = (matl & 1) * 8;
    const int ldr = tid >> 3, ldc = (tid & 7) * 8;

    auto load_stage = [&](int s, int k0) {
        __nv_bfloat16* sb = smb + s * 4 * S1;
        const int hh = k0 >> 6;
        const __nv_bfloat16* Ah = g_AOh + (((size_t)bb * NH + hh) * NS + loc0) * ND;
        const __nv_bfloat16* Al = g_AOl + (((size_t)bb * NH + hh) * NS + loc0) * ND;
        #pragma unroll
        for (int it = 0; it < 4; it++) {
            int r = ldr + it * 16;
            cpa16(sb +        r * KPAD + ldc, Ah + (size_t)r * ND + ldc);
            cpa16(sb + S1   + r * KPAD + ldc, Al + (size_t)r * ND + ldc);
            cpa16(sb + 2*S1 + r * KPAD + ldc, Wthg + (size_t)r * NE + k0 + ldc);
            cpa16(sb + 3*S1 + r * KPAD + ldc, Wtlg + (size_t)r * NE + k0 + ldc);
        }
        CP_COMMIT();
    };

    load_stage(0, 0);
    for (int i = 0; i < 4; i++) {
        if (i < 3) { load_stage((i + 1) & 1, (i + 1) * 64); CP_WAIT1(); }
        else       { CP_WAIT0(); }
        __syncthreads();

        const __nv_bfloat16* sb  = smb + (i & 1) * 4 * S1;
        const __nv_bfloat16* Xh  = sb;
        const __nv_bfloat16* Xl  = sb + S1;
        const __nv_bfloat16* Wth = sb + 2 * S1;
        const __nv_bfloat16* Wtl = sb + 3 * S1;

        #pragma unroll
        for (int kc = 0; kc < 4; kc++) {
            uint32_t ah[4], al[4];
            ldsm4(ah, Xh + a_off + kc * 16);
            ldsm4(al, Xl + a_off + kc * 16);
            #pragma unroll
            for (int jp = 0; jp < 4; jp++) {
                int boff = (jp * 16 + b_row) * KPAD + kc * 16 + b_kh;
                uint32_t bh[4], bl[4];
                ldsm4(bh, Wth + boff);
                ldsm4(bl, Wtl + boff);
                mma16816(acc[2*jp],   ah, bh[0], bh[1]);
                mma16816(acc[2*jp],   al, bh[0], bh[1]);
                mma16816(acc[2*jp],   ah, bl[0], bl[1]);
                mma16816(acc[2*jp+1], ah, bh[2], bh[3]);
                mma16816(acc[2*jp+1], al, bh[2], bh[3]);
                mma16816(acc[2*jp+1], ah, bl[2], bl[3]);
            }
        }
        __syncthreads();
    }

    const int g = lane >> 2;
    const int lr0 = loc0 + w4 * 16 + g;
    const int lr1 = lr0 + 8;
    {
        int row = bb * NS + idxp[lr0];
        bool live = (lr0 < cnt);
        #pragma unroll
        for (int j = 0; j < 8; j++) {
            int d = j * 8 + 2 * l4;
            float2 v = { live ? acc[j][0] + bo[n0 + d]     : 0.f,
                         live ? acc[j][1] + bo[n0 + d + 1] : 0.f };
            *(float2*)(out + (size_t)row * NE + n0 + d) = v;
        }
    }
    {
        int row = bb * NS + idxp[lr1];
        bool live = (lr1 < cnt);
        #pragma unroll
        for (int j = 0; j < 8; j++) {
            int d = j * 8 + 2 * l4;
            float2 v = { live ? acc[j][2] + bo[n0 + d]     : 0.f,
                         live ? acc[j][3] + bo[n0 + d + 1] : 0.f };
            *(float2*)(out + (size_t)row * NE + n0 + d) = v;
        }
    }
}

// ---------------------------------------------------------------------------
extern "C" void kernel_launch(void* const* d_in, const int* in_sizes, int n_in,
                              void* d_out, int out_size)
{
    const float* his     = (const float*)d_in[0];
    const int*   mask    = (const int*)d_in[1];
    const float* explore = (const float*)d_in[2];
    const float* exploit = (const float*)d_in[3];
    const float* Wq = (const float*)d_in[4];
    const float* bq = (const float*)d_in[5];
    const float* Wk = (const float*)d_in[6];
    const float* bk = (const float*)d_in[7];
    const float* Wv = (const float*)d_in[8];
    const float* bv = (const float*)d_in[9];
    const float* Wo = (const float*)d_in[10];
    const float* bo = (const float*)d_in[11];
    float* out = (float*)d_out;

    const int qkv_smem = QKV_SMEM_BF16 * 2;     // 73728 B
    const int op_smem  = OP_SMEM_BF16 * 2;      // 73728 B
    static bool attr_done = false;
    if (!attr_done) {
        cudaFuncSetAttribute(qkv_mma, cudaFuncAttributeMaxDynamicSharedMemorySize, qkv_smem);
        cudaFuncSetAttribute(out_proj_mma, cudaFuncAttributeMaxDynamicSharedMemorySize, op_smem);
        attr_done = true;
    }

    // single stream, 5 linear nodes — no events, no forks
    build_idx<<<NB, 1024>>>(mask);
    prep_xw<<<576, 256>>>(his, Wq, Wk, Wv, Wo);
    qkv_mma<<<dim3(NB * NS / 64, NH, 3), 128, qkv_smem>>>(bq, bk, bv);
    attn_mma<<<dim3(NS / 64, NH, NB), 256>>>(explore, exploit);
    out_proj_mma<<<dim3(NB * NS / 64, 4), 128, op_smem>>>(bo, out);
}

// round 16
// speedup vs baseline: 1.1467x; 1.0278x over previous
#include <cuda_runtime.h>
#include <cuda_bf16.h>
#include <cuda_fp16.h>
#include <cstdint>
#include <math.h>

#define NB 4
#define NS 2048
#define NE 256
#define NH 4
#define ND 64

// Scratch (allocation-free). All seq-indexed arrays in COMPACTED coordinates.
__device__ float g_Q[NB*NH*NS*ND];                                  // [b,h,i,d] fp32
__device__ __align__(16) __half g_Kf[NB*NH*NS*ND];                  // [b,h,i,d] fp16
__device__ __align__(16) __half g_Vf[NB*NH*ND*NS];                  // [b,h,d,i] fp16
__device__ __align__(16) __nv_bfloat16 g_AOh[NB*NH*NS*ND];          // [b,h,i,d]
__device__ __align__(16) __nv_bfloat16 g_AOl[NB*NH*NS*ND];
__device__ __align__(16) __nv_bfloat16 g_Wth[4*NE*NE];              // [mat][n][k]
__device__ __align__(16) __nv_bfloat16 g_Wtl[4*NE*NE];
__device__ __align__(16) __nv_bfloat16 g_Xh[NB*NS*NE];              // [b,i,k] pre-split X
__device__ __align__(16) __nv_bfloat16 g_Xl[NB*NS*NE];
__device__ int g_idx[NB*NS];     // [0..cnt) unmasked orig s; [cnt..NS) masked orig s
__device__ int g_cnt[NB];

__device__ __forceinline__ uint32_t pack_bf16x2(float a, float b) {
    __nv_bfloat162 t = __floats2bfloat162_rn(a, b);   // a -> low half
    return *(uint32_t*)&t;
}
__device__ __forceinline__ uint32_t pack_h2(float a, float b) {
    __half2 t = __floats2half2_rn(a, b);              // a -> low half
    return *(uint32_t*)&t;
}
__device__ __forceinline__ void split_hi_lo(float x, float& hi, float& lo) {
    __nv_bfloat16 h = __float2bfloat16_rn(x);
    hi = __bfloat162float(h);
    lo = x - hi;
}

// mma.sync m16n8k16 row.col (sm_80+ PTX, no arch suffix)
__device__ __forceinline__ void mma16816(float c[4], const uint32_t a[4],
                                         uint32_t b0, uint32_t b1) {
    asm volatile(
        "mma.sync.aligned.m16n8k16.row.col.f32.bf16.bf16.f32 "
        "{%0,%1,%2,%3}, {%4,%5,%6,%7}, {%8,%9}, {%0,%1,%2,%3};"
        : "+f"(c[0]), "+f"(c[1]), "+f"(c[2]), "+f"(c[3])
        : "r"(a[0]), "r"(a[1]), "r"(a[2]), "r"(a[3]), "r"(b0), "r"(b1));
}
__device__ __forceinline__ void mma16816h(float c[4], const uint32_t a[4],
                                          uint32_t b0, uint32_t b1) {
    asm volatile(
        "mma.sync.aligned.m16n8k16.row.col.f32.f16.f16.f32 "
        "{%0,%1,%2,%3}, {%4,%5,%6,%7}, {%8,%9}, {%0,%1,%2,%3};"
        : "+f"(c[0]), "+f"(c[1]), "+f"(c[2]), "+f"(c[3])
        : "r"(a[0]), "r"(a[1]), "r"(a[2]), "r"(a[3]), "r"(b0), "r"(b1));
}

// ldmatrix x4 (sm_75+)
__device__ __forceinline__ void ldsm4(uint32_t r[4], const void* p) {
    uint32_t a = (uint32_t)__cvta_generic_to_shared(p);
    asm volatile("ldmatrix.sync.aligned.m8n8.x4.shared.b16 {%0,%1,%2,%3}, [%4];"
                 : "=r"(r[0]), "=r"(r[1]), "=r"(r[2]), "=r"(r[3]) : "r"(a));
}

// cp.async 16B (sm_80+)
__device__ __forceinline__ void cpa16(void* dst, const void* src) {
    uint32_t d = (uint32_t)__cvta_generic_to_shared(dst);
    asm volatile("cp.async.cg.shared.global [%0], [%1], 16;" :: "r"(d), "l"(src));
}
#define CP_COMMIT() asm volatile("cp.async.commit_group;")
#define CP_WAIT1()  asm volatile("cp.async.wait_group 1;")
#define CP_WAIT0()  asm volatile("cp.async.wait_group 0;")

#define KPAD 72   // 16-bit row stride; 36-word stride -> conflict-free ldmatrix rows
#define S1 (64*KPAD)

// ---------------------------------------------------------------------------
// Kernel A: per-batch compaction index. Unmasked -> [0,cnt), masked -> [cnt,NS).
// ---------------------------------------------------------------------------
__global__ __launch_bounds__(1024) void build_idx(const int* __restrict__ mask)
{
    __shared__ int scan[1024];
    const int b = blockIdx.x;
    const int tid = threadIdx.x;
    const int s0 = 2 * tid, s1 = 2 * tid + 1;
    const int m0 = (mask[b * NS + s0] == 0) ? 1 : 0;
    const int m1 = (mask[b * NS + s1] == 0) ? 1 : 0;
    scan[tid] = m0 + m1;
    __syncthreads();
    #pragma unroll
    for (int off = 1; off < 1024; off <<= 1) {
        int v = (tid >= off) ? scan[tid - off] : 0;
        __syncthreads();
        scan[tid] += v;
        __syncthreads();
    }
    const int excl = scan[tid] - m0 - m1;
    const int total = scan[1023];
    if (m0) g_idx[b * NS + excl] = s0;
    else    g_idx[b * NS + total + (s0 - excl)] = s0;
    if (m1) g_idx[b * NS + excl + m0] = s1;
    else    g_idx[b * NS + total + (s1 - excl - m0)] = s1;
    if (tid == 0) g_cnt[b] = total;
}

// ---------------------------------------------------------------------------
// Kernel A2: fused prep_x (blocks 0..511) + prep_w (blocks 512..575).
// ---------------------------------------------------------------------------
__global__ __launch_bounds__(256) void prep_xw(
    const float* __restrict__ X,
    const float* __restrict__ Wq, const float* __restrict__ Wk,
    const float* __restrict__ Wv, const float* __restrict__ Wo)
{
    __shared__ float t[64][65];
    const int tid = threadIdx.x;

    if (blockIdx.x < 512) {
        const int m0 = blockIdx.x * 16;
        const int bb = m0 >> 11, loc0 = m0 & (NS - 1);
        const int cnt = g_cnt[bb];
        if (loc0 >= cnt) return;
        const int* idxp = g_idx + bb * NS;

        #pragma unroll
        for (int it = 0; it < 4; it++) {
            int idx = tid + it * 256;
            int r = idx >> 6, c4 = (idx & 63) * 4;
            int src = idxp[loc0 + r];
            float4 v = *(const float4*)(X + ((size_t)bb * NS + src) * NE + c4);
            float h0,l0,h1,l1,h2,l2,h3,l3;
            split_hi_lo(v.x,h0,l0); split_hi_lo(v.y,h1,l1);
            split_hi_lo(v.z,h2,l2); split_hi_lo(v.w,h3,l3);
            size_t o = ((size_t)bb * NS + loc0 + r) * NE + c4;
            uint32_t hw[2] = { pack_bf16x2(h0,h1), pack_bf16x2(h2,h3) };
            uint32_t lw[2] = { pack_bf16x2(l0,l1), pack_bf16x2(l2,l3) };
            *(uint2*)(g_Xh + o) = *(uint2*)hw;
            *(uint2*)(g_Xl + o) = *(uint2*)lw;
        }
    } else {
        const int bidx = blockIdx.x - 512;
        const int mt = bidx >> 4;
        const int k0 = ((bidx >> 2) & 3) * 64, n0 = (bidx & 3) * 64;
        const float* Ws[4] = { Wq, Wk, Wv, Wo };
        const float* W = Ws[mt];

        #pragma unroll
        for (int it = 0; it < 16; it++) {
            int idx = tid + it * 256;
            int kk = idx >> 6, nn = idx & 63;
            t[kk][nn] = W[(k0 + kk) * NE + n0 + nn];
        }
        __syncthreads();

        #pragma unroll
        for (int it = 0; it < 2; it++) {
            int idx = tid + it * 256;
            int n = idx >> 3, c8 = (idx & 7) * 8;
            uint32_t hw[4], lw[4];
            #pragma unroll
            for (int p = 0; p < 4; p++) {
                float hi0, lo0, hi1, lo1;
                split_hi_lo(t[c8 + 2*p][n],     hi0, lo0);
                split_hi_lo(t[c8 + 2*p + 1][n], hi1, lo1);
                hw[p] = pack_bf16x2(hi0, hi1);
                lw[p] = pack_bf16x2(lo0, lo1);
            }
            size_t o = (size_t)mt * NE * NE + (size_t)(n0 + n) * NE + k0 + c8;
            *(uint4*)(g_Wth + o) = *(uint4*)hw;
            *(uint4*)(g_Wtl + o) = *(uint4*)lw;
        }
    }
}

// ---------------------------------------------------------------------------
// Kernel 1: QKV projection, one weight matrix per blockIdx.z.
// cp.async 2-stage pipeline, ldmatrix fragments.
// ---------------------------------------------------------------------------
#define QKV_SMEM_BF16 (2 * 4 * S1)    // 73728 B

__global__ __launch_bounds__(128, 3) void qkv_mma(
    const float* __restrict__ bq, const float* __restrict__ bk,
    const float* __restrict__ bv)
{
    extern __shared__ __nv_bfloat16 smb[];

    const int tid  = threadIdx.x;
    const int w4   = tid >> 5;
    const int lane = tid & 31;
    const int l4   = lane & 3;
    const int matl = lane >> 3;
    const int rowl = lane & 7;
    const int m0   = blockIdx.x * 64;
    const int h    = blockIdx.y;
    const int mt   = blockIdx.z;
    const int n0   = h * 64;

    const int bb   = m0 >> 11;
    const int loc0 = m0 & (NS - 1);
    const int cnt  = g_cnt[bb];
    if (loc0 >= cnt) return;

    const __nv_bfloat16* Xhg = g_Xh + ((size_t)bb * NS + loc0) * NE;
    const __nv_bfloat16* Xlg = g_Xl + ((size_t)bb * NS + loc0) * NE;
    const __nv_bfloat16* Wthg = g_Wth + (size_t)mt * NE * NE + (size_t)n0 * NE;
    const __nv_bfloat16* Wtlg = g_Wtl + (size_t)mt * NE * NE + (size_t)n0 * NE;

    float acc[8][4];
    #pragma unroll
    for (int j = 0; j < 8; j++)
        #pragma unroll
        for (int c = 0; c < 4; c++) acc[j][c] = 0.f;

    const int a_off = (w4 * 16 + (matl & 1) * 8 + rowl) * KPAD + (matl >> 1) * 8;
    const int b_row = (matl >> 1) * 8 + rowl;
    const int b_kh  = (matl & 1) * 8;

    const int ldr = tid >> 3, ldc = (tid & 7) * 8;

    auto load_stage = [&](int s, int k0) {
        __nv_bfloat16* sb = smb + s * 4 * S1;
        #pragma unroll
        for (int it = 0; it < 4; it++) {
            int r = ldr + it * 16;
            cpa16(sb +        r * KPAD + ldc, Xhg  + (size_t)r * NE + k0 + ldc);
            cpa16(sb + S1   + r * KPAD + ldc, Xlg  + (size_t)r * NE + k0 + ldc);
            cpa16(sb + 2*S1 + r * KPAD + ldc, Wthg + (size_t)r * NE + k0 + ldc);
            cpa16(sb + 3*S1 + r * KPAD + ldc, Wtlg + (size_t)r * NE + k0 + ldc);
        }
        CP_COMMIT();
    };

    load_stage(0, 0);
    for (int i = 0; i < 4; i++) {
        if (i < 3) { load_stage((i + 1) & 1, (i + 1) * 64); CP_WAIT1(); }
        else       { CP_WAIT0(); }
        __syncthreads();

        const __nv_bfloat16* sb  = smb + (i & 1) * 4 * S1;
        const __nv_bfloat16* Xh  = sb;
        const __nv_bfloat16* Xl  = sb + S1;
        const __nv_bfloat16* Wth = sb + 2 * S1;
        const __nv_bfloat16* Wtl = sb + 3 * S1;

        #pragma unroll
        for (int kc = 0; kc < 4; kc++) {
            uint32_t ah[4], al[4];
            ldsm4(ah, Xh + a_off + kc * 16);
            ldsm4(al, Xl + a_off + kc * 16);
            #pragma unroll
            for (int jp = 0; jp < 4; jp++) {
                int boff = (jp * 16 + b_row) * KPAD + kc * 16 + b_kh;
                uint32_t bh[4], bl[4];
                ldsm4(bh, Wth + boff);
                ldsm4(bl, Wtl + boff);
                mma16816(acc[2*jp],   ah, bh[0], bh[1]);
                mma16816(acc[2*jp],   al, bh[0], bh[1]);
                mma16816(acc[2*jp],   ah, bl[0], bl[1]);
                mma16816(acc[2*jp+1], ah, bh[2], bh[3]);
                mma16816(acc[2*jp+1], al, bh[2], bh[3]);
                mma16816(acc[2*jp+1], ah, bl[2], bl[3]);
            }
        }
        __syncthreads();
    }

    const int g = lane >> 2;
    const int s0 = loc0 + w4 * 16 + g;
    const int s1 = s0 + 8;

    if (mt == 0) {              // ---- Q: fp32 ----
        float* O0 = g_Q + (((size_t)bb * NH + h) * NS + s0) * ND;
        float* O1 = g_Q + (((size_t)bb * NH + h) * NS + s1) * ND;
        #pragma unroll
        for (int j = 0; j < 8; j++) {
            int d = j * 8 + 2 * l4;
            float bx = bq[n0 + d], by = bq[n0 + d + 1];
            float2 v0 = { acc[j][0] + bx, acc[j][1] + by };
            float2 v1 = { acc[j][2] + bx, acc[j][3] + by };
            *(float2*)(O0 + d) = v0;
            *(float2*)(O1 + d) = v1;
        }
    } else if (mt == 1) {       // ---- K: fp16 ----
        size_t o0 = (((size_t)bb * NH + h) * NS + s0) * ND;
        size_t o1 = (((size_t)bb * NH + h) * NS + s1) * ND;
        #pragma unroll
        for (int j = 0; j < 8; j++) {
            int d = j * 8 + 2 * l4;
            float bx = bk[n0 + d], by = bk[n0 + d + 1];
            *(uint32_t*)(g_Kf + o0 + d) = pack_h2(acc[j][0] + bx, acc[j][1] + by);
            *(uint32_t*)(g_Kf + o1 + d) = pack_h2(acc[j][2] + bx, acc[j][3] + by);
        }
    } else {                    // ---- V: transpose via smem, fp16 [b,h,d,i] ----
        #define VPAD 68
        float* Vb = (float*)smb;
        __syncthreads();
        #pragma unroll
        for (int j = 0; j < 8; j++) {
            int d = j * 8 + 2 * l4;
            float bx = bv[n0 + d], by = bv[n0 + d + 1];
            int sr0 = w4 * 16 + g, sr1 = sr0 + 8;
            Vb[(d    ) * VPAD + sr0] = acc[j][0] + bx;
            Vb[(d + 1) * VPAD + sr0] = acc[j][1] + by;
            Vb[(d    ) * VPAD + sr1] = acc[j][2] + bx;
            Vb[(d + 1) * VPAD + sr1] = acc[j][3] + by;
        }
        __syncthreads();
        #pragma unroll
        for (int it = 0; it < 8; it++) {
            int idx = tid + it * 128;
            int d = idx >> 4, c4 = (idx & 15) * 4;
            int s = loc0 + c4;
            size_t o = (((size_t)bb * NH + h) * ND + d) * NS + s;
            uint32_t hw[2] = { pack_h2(Vb[d * VPAD + c4],     Vb[d * VPAD + c4 + 1]),
                               pack_h2(Vb[d * VPAD + c4 + 2], Vb[d * VPAD + c4 + 3]) };
            *(uint2*)(g_Vf + o) = *(uint2*)hw;
        }
    }
}

// ---------------------------------------------------------------------------
// Kernel 2: flash attention, q-tile 64, 2 warpgroups split over K-tiles,
// cp.async double-buffered K/V, register penalties.
// Dyn smem: [wg0K0|wg0K1|wg1K0|wg1K1|wg0V0|wg0V1|wg1V0|wg1V1], each S1 halves.
// ---------------------------------------------------------------------------
#define ATTN_SMEM_B (8 * S1 * 2)   // 73728 B

__global__ __launch_bounds__(256, 2) void attn_mma(
    const float* __restrict__ explore,
    const float* __restrict__ exploit)
{
    extern __shared__ __half smh[];

    const int tid  = threadIdx.x;
    const int w    = tid >> 5;
    const int wg   = w >> 2;
    const int w4   = w & 3;
    const int wtid = tid & 127;
    const int lane = tid & 31;
    const int g    = lane >> 2;
    const int l4   = lane & 3;
    const int matl = lane >> 3;
    const int rowl = lane & 7;
    const int q0   = blockIdx.x * 64;
    const int h    = blockIdx.y, b = blockIdx.z;

    const int cnt = g_cnt[b];
    if (q0 >= cnt) return;
    const int* idxp = g_idx + b * NS;
    const int NT = (cnt + 63) >> 6;

    const size_t base = ((size_t)b * NH + h) * NS * ND;
    const float* Qp = g_Q + base;
    const __half* Kp = g_Kf + base;
    const __half* Vp = g_Vf + base;

    const int r0 = w4 * 16 + g;
    const int r1 = r0 + 8;
    const int cq0 = q0 + r0, cq1 = q0 + r1;
    const int so0 = idxp[cq0], so1 = idxp[cq1];
    float rs0, rs1;
    {
        float t0 = 1.0f + 0.5f * explore[b * NS + so0] - 0.5f * exploit[b * NS + so0];
        t0 = fminf(fmaxf(t0, 0.5f), 2.0f);
        rs0 = 0.125f / t0;
        float t1 = 1.0f + 0.5f * explore[b * NS + so1] - 0.5f * exploit[b * NS + so1];
        t1 = fminf(fmaxf(t1, 0.5f), 2.0f);
        rs1 = 0.125f / t1;
    }

    uint32_t qf[4][4];
    #pragma unroll
    for (int kc = 0; kc < 4; kc++) {
        int d0 = kc * 16 + l4 * 2;
        const float2 a00 = *(const float2*)(Qp + (size_t)cq0 * ND + d0);
        const float2 a10 = *(const float2*)(Qp + (size_t)cq1 * ND + d0);
        const float2 a01 = *(const float2*)(Qp + (size_t)cq0 * ND + d0 + 8);
        const float2 a11 = *(const float2*)(Qp + (size_t)cq1 * ND + d0 + 8);
        qf[kc][0] = pack_h2(a00.x * rs0, a00.y * rs0);
        qf[kc][1] = pack_h2(a10.x * rs1, a10.y * rs1);
        qf[kc][2] = pack_h2(a01.x * rs0, a01.y * rs0);
        qf[kc][3] = pack_h2(a11.x * rs1, a11.y * rs1);
    }

    float oacc[8][4];
    #pragma unroll
    for (int j = 0; j < 8; j++)
        #pragma unroll
        for (int c = 0; c < 4; c++) oacc[j][c] = 0.f;
    float lsum0 = 0.f, lsum1 = 0.f;

    const int b_row = (matl >> 1) * 8 + rowl;
    const int b_kh  = (matl & 1) * 8;
    const int ldr = wtid >> 3, ldc = (wtid & 7) * 8;

    // tiles for this wg: kt = wg, wg+2, ...
    const int ntw = (NT - wg + 1) >> 1;

    auto load_tile = [&](int buf, int kt) {
        __half* Kd = smh + ((size_t)(wg * 2 + buf)) * S1;
        __half* Vd = smh + ((size_t)(4 + wg * 2 + buf)) * S1;
        const int kk0 = kt * 64;
        #pragma unroll
        for (int it = 0; it < 4; it++) {
            int r = ldr + it * 16;
            cpa16(Kd + r * KPAD + ldc, Kp + (size_t)(kk0 + r) * ND + ldc);
            cpa16(Vd + r * KPAD + ldc, Vp + (size_t)r * NS + kk0 + ldc);
        }
        CP_COMMIT();
    };

    if (ntw > 0) load_tile(0, wg);
    for (int ii = 0; ii < ntw; ii++) {
        const int kt = wg + 2 * ii;
        const int kk0 = kt * 64;
        if (ii + 1 < ntw) { load_tile((ii + 1) & 1, kt + 2); CP_WAIT1(); }
        else              { CP_WAIT0(); }
        asm volatile("bar.sync %0, %1;" :: "r"(wg + 1), "r"(128) : "memory");

        const __half* Ksw = smh + ((size_t)(wg * 2 + (ii & 1))) * S1;
        const __half* Vsw = smh + ((size_t)(4 + wg * 2 + (ii & 1))) * S1;

        float sacc[8][4];
        #pragma unroll
        for (int j = 0; j < 8; j++)
            #pragma unroll
            for (int c = 0; c < 4; c++) sacc[j][c] = 0.f;

        #pragma unroll
        for (int kc = 0; kc < 4; kc++) {
            #pragma unroll
            for (int jp = 0; jp < 4; jp++) {
                uint32_t kb[4];
                ldsm4(kb, Ksw + (jp * 16 + b_row) * KPAD + kc * 16 + b_kh);
                mma16816h(sacc[2*jp],   qf[kc], kb[0], kb[1]);
                mma16816h(sacc[2*jp+1], qf[kc], kb[2], kb[3]);
            }
        }

        uint32_t ps[8][2];
        #pragma unroll
        for (int j = 0; j < 8; j++) {
            int col = kk0 + j * 8 + l4 * 2;
            float px = (col     < cnt) ? -11.0f : -1e30f;
            float py = (col + 1 < cnt) ? -11.0f : -1e30f;
            float p0 = __expf(sacc[j][0] + px);
            float p1 = __expf(sacc[j][1] + py);
            float p2 = __expf(sacc[j][2] + px);
            float p3 = __expf(sacc[j][3] + py);
            lsum0 += p0 + p1;
            lsum1 += p2 + p3;
            ps[j][0] = pack_h2(p0, p1);
            ps[j][1] = pack_h2(p2, p3);
        }

        #pragma unroll
        for (int kc = 0; kc < 4; kc++) {
            uint32_t Af[4] = { ps[2*kc][0], ps[2*kc][1], ps[2*kc+1][0], ps[2*kc+1][1] };
            #pragma unroll
            for (int jp = 0; jp < 4; jp++) {
                uint32_t vb[4];
                ldsm4(vb, Vsw + (jp * 16 + b_row) * KPAD + kc * 16 + b_kh);
                mma16816h(oacc[2*jp],   Af, vb[0], vb[1]);
                mma16816h(oacc[2*jp+1], Af, vb[2], vb[3]);
            }
        }
        asm volatile("bar.sync %0, %1;" :: "r"(wg + 1), "r"(128) : "memory");
    }

    lsum0 += __shfl_xor_sync(0xffffffffu, lsum0, 1);
    lsum0 += __shfl_xor_sync(0xffffffffu, lsum0, 2);
    lsum1 += __shfl_xor_sync(0xffffffffu, lsum1, 1);
    lsum1 += __shfl_xor_sync(0xffffffffu, lsum1, 2);

    // ---- combine wg partials through smem (overlay on wg0 K buffers) ----
    __syncthreads();
    float* Ob = (float*)smh;                 // 64 x 66 floats
    float* Lb = Ob + 64 * 66;                // 64 floats
    if (wg == 1) {
        #pragma unroll
        for (int j = 0; j < 8; j++) {
            int col = j * 8 + 2 * l4;
            Ob[r0 * 66 + col]     = oacc[j][0];
            Ob[r0 * 66 + col + 1] = oacc[j][1];
            Ob[r1 * 66 + col]     = oacc[j][2];
            Ob[r1 * 66 + col + 1] = oacc[j][3];
        }
        if (l4 == 0) { Lb[r0] = lsum0; Lb[r1] = lsum1; }
    }
    __syncthreads();
    if (wg == 0) {
        lsum0 += Lb[r0];
        lsum1 += Lb[r1];
        float inv0 = (lsum0 > 0.f) ? 1.f / lsum0 : 0.f;
        float inv1 = (lsum1 > 0.f) ? 1.f / lsum1 : 0.f;
        if (cq0 < cnt) {
            size_t o0 = base + (size_t)cq0 * ND;
            #pragma unroll
            for (int j = 0; j < 8; j++) {
                int col = j * 8 + 2 * l4;
                float v0 = (oacc[j][0] + Ob[r0 * 66 + col])     * inv0;
                float v1 = (oacc[j][1] + Ob[r0 * 66 + col + 1]) * inv0;
                float h0,l0,h1,l1;
                split_hi_lo(v0, h0, l0); split_hi_lo(v1, h1, l1);
                *(uint32_t*)(g_AOh + o0 + col) = pack_bf16x2(h0, h1);
                *(uint32_t*)(g_AOl + o0 + col) = pack_bf16x2(l0, l1);
            }
        }
        if (cq1 < cnt) {
            size_t o1 = base + (size_t)cq1 * ND;
            #pragma unroll
            for (int j = 0; j < 8; j++) {
                int col = j * 8 + 2 * l4;
                float v0 = (oacc[j][2] + Ob[r1 * 66 + col])     * inv1;
                float v1 = (oacc[j][3] + Ob[r1 * 66 + col + 1]) * inv1;
                float h0,l0,h1,l1;
                split_hi_lo(v0, h0, l0); split_hi_lo(v1, h1, l1);
                *(uint32_t*)(g_AOh + o1 + col) = pack_bf16x2(h0, h1);
                *(uint32_t*)(g_AOl + o1 + col) = pack_bf16x2(l0, l1);
            }
        }
    }
}

// ---------------------------------------------------------------------------
// Kernel 3: output projection + masked-row zeroing (tail/partial blocks).
// ---------------------------------------------------------------------------
#define OP_SMEM_BF16 (2 * 4 * S1)    // 73728 B

__global__ __launch_bounds__(128, 3) void out_proj_mma(
    const float* __restrict__ bo,
    float* __restrict__ out)
{
    extern __shared__ __nv_bfloat16 smb[];

    const int tid  = threadIdx.x;
    const int w4   = tid >> 5;
    const int lane = tid & 31;
    const int l4   = lane & 3;
    const int matl = lane >> 3;
    const int rowl = lane & 7;
    const int m0   = blockIdx.x * 64;
    const int n0   = blockIdx.y * 64;

    const int bb   = m0 >> 11;
    const int loc0 = m0 & (NS - 1);
    const int cnt  = g_cnt[bb];
    const int* idxp = g_idx + bb * NS;

    if (loc0 >= cnt) {
        #pragma unroll
        for (int it = 0; it < 8; it++) {
            int idx = tid + it * 128;
            int r = idx >> 4, c4 = (idx & 15) * 4;
            int row = bb * NS + idxp[loc0 + r];
            float4 z = {0.f, 0.f, 0.f, 0.f};
            *(float4*)(out + (size_t)row * NE + n0 + c4) = z;
        }
        return;
    }

    const __nv_bfloat16* Wthg = g_Wth + (size_t)3 * NE * NE + (size_t)n0 * NE;
    const __nv_bfloat16* Wtlg = g_Wtl + (size_t)3 * NE * NE + (size_t)n0 * NE;

    float acc[8][4];
    #pragma unroll
    for (int j = 0; j < 8; j++)
        #pragma unroll
        for (int c = 0; c < 4; c++) acc[j][c] = 0.f;

    const int a_off = (w4 * 16 + (matl & 1) * 8 + rowl) * KPAD + (matl >> 1) * 8;
    const int b_row = (matl >> 1) * 8 + rowl;
    const int b_kh  = (matl & 1) * 8;
    const int ldr = tid >> 3, ldc = (tid & 7) * 8;

    auto load_stage = [&](int s, int k0) {
        __nv_bfloat16* sb = smb + s * 4 * S1;
        const int hh = k0 >> 6;
        const __nv_bfloat16* Ah = g_AOh + (((size_t)bb * NH + hh) * NS + loc0) * ND;
        const __nv_bfloat16* Al = g_AOl + (((size_t)bb * NH + hh) * NS + loc0) * ND;
        #pragma unroll
        for (int it = 0; it < 4; it++) {
            int r = ldr + it * 16;
            cpa16(sb +        r * KPAD + ldc, Ah + (size_t)r * ND + ldc);
            cpa16(sb + S1   + r * KPAD + ldc, Al + (size_t)r * ND + ldc);
            cpa16(sb + 2*S1 + r * KPAD + ldc, Wthg + (size_t)r * NE + k0 + ldc);
            cpa16(sb + 3*S1 + r * KPAD + ldc, Wtlg + (size_t)r * NE + k0 + ldc);
        }
        CP_COMMIT();
    };

    load_stage(0, 0);
    for (int i = 0; i < 4; i++) {
        if (i < 3) { load_stage((i + 1) & 1, (i + 1) * 64); CP_WAIT1(); }
        else       { CP_WAIT0(); }
        __syncthreads();

        const __nv_bfloat16* sb  = smb + (i & 1) * 4 * S1;
        const __nv_bfloat16* Xh  = sb;
        const __nv_bfloat16* Xl  = sb + S1;
        const __nv_bfloat16* Wth = sb + 2 * S1;
        const __nv_bfloat16* Wtl = sb + 3 * S1;

        #pragma unroll
        for (int kc = 0; kc < 4; kc++) {
            uint32_t ah[4], al[4];
            ldsm4(ah, Xh + a_off + kc * 16);
            ldsm4(al, Xl + a_off + kc * 16);
            #pragma unroll
            for (int jp = 0; jp < 4; jp++) {
                int boff = (jp * 16 + b_row) * KPAD + kc * 16 + b_kh;
                uint32_t bh[4], bl[4];
                ldsm4(bh, Wth + boff);
                ldsm4(bl, Wtl + boff);
                mma16816(acc[2*jp],   ah, bh[0], bh[1]);
                mma16816(acc[2*jp],   al, bh[0], bh[1]);
                mma16816(acc[2*jp],   ah, bl[0], bl[1]);
                mma16816(acc[2*jp+1], ah, bh[2], bh[3]);
                mma16816(acc[2*jp+1], al, bh[2], bh[3]);
                mma16816(acc[2*jp+1], ah, bl[2], bl[3]);
            }
        }
        __syncthreads();
    }

    const int g = lane >> 2;
    const int lr0 = loc0 + w4 * 16 + g;
    const int lr1 = lr0 + 8;
    {
        int row = bb * NS + idxp[lr0];
        bool live = (lr0 < cnt);
        #pragma unroll
        for (int j = 0; j < 8; j++) {
            int d = j * 8 + 2 * l4;
            float2 v = { live ? acc[j][0] + bo[n0 + d]     : 0.f,
                         live ? acc[j][1] + bo[n0 + d + 1] : 0.f };
            *(float2*)(out + (size_t)row * NE + n0 + d) = v;
        }
    }
    {
        int row = bb * NS + idxp[lr1];
        bool live = (lr1 < cnt);
        #pragma unroll
        for (int j = 0; j < 8; j++) {
            int d = j * 8 + 2 * l4;
            float2 v = { live ? acc[j][2] + bo[n0 + d]     : 0.f,
                         live ? acc[j][3] + bo[n0 + d + 1] : 0.f };
            *(float2*)(out + (size_t)row * NE + n0 + d) = v;
        }
    }
}

// ---------------------------------------------------------------------------
extern "C" void kernel_launch(void* const* d_in, const int* in_sizes, int n_in,
                              void* d_out, int out_size)
{
    const float* his     = (const float*)d_in[0];
    const int*   mask    = (const int*)d_in[1];
    const float* explore = (const float*)d_in[2];
    const float* exploit = (const float*)d_in[3];
    const float* Wq = (const float*)d_in[4];
    const float* bq = (const float*)d_in[5];
    const float* Wk = (const float*)d_in[6];
    const float* bk = (const float*)d_in[7];
    const float* Wv = (const float*)d_in[8];
    const float* bv = (const float*)d_in[9];
    const float* Wo = (const float*)d_in[10];
    const float* bo = (const float*)d_in[11];
    float* out = (float*)d_out;

    const int qkv_smem  = QKV_SMEM_BF16 * 2;    // 73728 B
    const int op_smem   = OP_SMEM_BF16 * 2;     // 73728 B
    const int attn_smem = ATTN_SMEM_B;          // 73728 B
    static bool attr_done = false;
    if (!attr_done) {
        cudaFuncSetAttribute(qkv_mma, cudaFuncAttributeMaxDynamicSharedMemorySize, qkv_smem);
        cudaFuncSetAttribute(out_proj_mma, cudaFuncAttributeMaxDynamicSharedMemorySize, op_smem);
        cudaFuncSetAttribute(attn_mma, cudaFuncAttributeMaxDynamicSharedMemorySize, attn_smem);
        attr_done = true;
    }

    // single stream, 5 linear nodes
    build_idx<<<NB, 1024>>>(mask);
    prep_xw<<<576, 256>>>(his, Wq, Wk, Wv, Wo);
    qkv_mma<<<dim3(NB * NS / 64, NH, 3), 128, qkv_smem>>>(bq, bk, bv);
    attn_mma<<<dim3(NS / 64, NH, NB), 256, attn_smem>>>(explore, exploit);
    out_proj_mma<<<dim3(NB * NS / 64, 4), 128, op_smem>>>(bo, out);
}

// round 17
// speedup vs baseline: 1.1484x; 1.0015x over previous
#include <cuda_runtime.h>
#include <cuda_bf16.h>
#include <cuda_fp16.h>
#include <cstdint>
#include <math.h>

#define NB 4
#define NS 2048
#define NE 256
#define NH 4
#define ND 64

// Scratch (allocation-free). All seq-indexed arrays in COMPACTED coordinates.
__device__ float g_Q[NB*NH*NS*ND];                                  // [b,h,i,d] fp32
__device__ __align__(16) __half g_Kf[NB*NH*NS*ND];                  // [b,h,i,d] fp16
__device__ __align__(16) __half g_Vf[NB*NH*ND*NS];                  // [b,h,d,i] fp16
__device__ __align__(16) __nv_bfloat16 g_AOh[NB*NH*NS*ND];          // [b,h,i,d]
__device__ __align__(16) __nv_bfloat16 g_AOl[NB*NH*NS*ND];
__device__ __align__(16) __nv_bfloat16 g_Wth[4*NE*NE];              // [mat][n][k]
__device__ __align__(16) __nv_bfloat16 g_Wtl[4*NE*NE];
__device__ __align__(16) __nv_bfloat16 g_Xh[NB*NS*NE];              // [b,i,k] pre-split X
__device__ __align__(16) __nv_bfloat16 g_Xl[NB*NS*NE];
__device__ int g_idx[NB*NS];     // [0..cnt) unmasked orig s; [cnt..NS) masked orig s
__device__ int g_cnt[NB];

__device__ __forceinline__ uint32_t pack_bf16x2(float a, float b) {
    __nv_bfloat162 t = __floats2bfloat162_rn(a, b);   // a -> low half
    return *(uint32_t*)&t;
}
__device__ __forceinline__ uint32_t pack_h2(float a, float b) {
    __half2 t = __floats2half2_rn(a, b);              // a -> low half
    return *(uint32_t*)&t;
}
__device__ __forceinline__ void split_hi_lo(float x, float& hi, float& lo) {
    __nv_bfloat16 h = __float2bfloat16_rn(x);
    hi = __bfloat162float(h);
    lo = x - hi;
}
__device__ __forceinline__ float ex2(float x) {
    float r;
    asm("ex2.approx.ftz.f32 %0, %1;" : "=f"(r) : "f"(x));
    return r;
}

// mma.sync m16n8k16 row.col (sm_80+ PTX, no arch suffix)
__device__ __forceinline__ void mma16816(float c[4], const uint32_t a[4],
                                         uint32_t b0, uint32_t b1) {
    asm volatile(
        "mma.sync.aligned.m16n8k16.row.col.f32.bf16.bf16.f32 "
        "{%0,%1,%2,%3}, {%4,%5,%6,%7}, {%8,%9}, {%0,%1,%2,%3};"
        : "+f"(c[0]), "+f"(c[1]), "+f"(c[2]), "+f"(c[3])
        : "r"(a[0]), "r"(a[1]), "r"(a[2]), "r"(a[3]), "r"(b0), "r"(b1));
}
__device__ __forceinline__ void mma16816h(float c[4], const uint32_t a[4],
                                          uint32_t b0, uint32_t b1) {
    asm volatile(
        "mma.sync.aligned.m16n8k16.row.col.f32.f16.f16.f32 "
        "{%0,%1,%2,%3}, {%4,%5,%6,%7}, {%8,%9}, {%0,%1,%2,%3};"
        : "+f"(c[0]), "+f"(c[1]), "+f"(c[2]), "+f"(c[3])
        : "r"(a[0]), "r"(a[1]), "r"(a[2]), "r"(a[3]), "r"(b0), "r"(b1));
}

// ldmatrix x4 (sm_75+)
__device__ __forceinline__ void ldsm4(uint32_t r[4], const void* p) {
    uint32_t a = (uint32_t)__cvta_generic_to_shared(p);
    asm volatile("ldmatrix.sync.aligned.m8n8.x4.shared.b16 {%0,%1,%2,%3}, [%4];"
                 : "=r"(r[0]), "=r"(r[1]), "=r"(r[2]), "=r"(r[3]) : "r"(a));
}

// cp.async 16B (sm_80+)
__device__ __forceinline__ void cpa16(void* dst, const void* src) {
    uint32_t d = (uint32_t)__cvta_generic_to_shared(dst);
    asm volatile("cp.async.cg.shared.global [%0], [%1], 16;" :: "r"(d), "l"(src));
}
#define CP_COMMIT() asm volatile("cp.async.commit_group;")
#define CP_WAIT1()  asm volatile("cp.async.wait_group 1;")
#define CP_WAIT0()  asm volatile("cp.async.wait_group 0;")

#define KPAD 72   // 16-bit row stride; 36-word stride -> conflict-free ldmatrix rows
#define S1 (64*KPAD)
#define LOG2E 1.44269504f

// ---------------------------------------------------------------------------
// Kernel A: per-batch compaction index via warp scans (2 barriers total).
// Unmasked -> [0,cnt), masked -> [cnt,NS).
// ---------------------------------------------------------------------------
__global__ __launch_bounds__(256) void build_idx(const int* __restrict__ mask)
{
    __shared__ int warp_tot[8];
    __shared__ int warp_off[8];
    __shared__ int s_total;

    const int b = blockIdx.x;
    const int tid = threadIdx.x;
    const int w = tid >> 5, lane = tid & 31;
    const int base = tid * 8;

    int4 a0 = *(const int4*)(mask + b * NS + base);
    int4 a1 = *(const int4*)(mask + b * NS + base + 4);
    int m[8] = { a0.x == 0, a0.y == 0, a0.z == 0, a0.w == 0,
                 a1.x == 0, a1.y == 0, a1.z == 0, a1.w == 0 };
    int pre[8]; int c = 0;
    #pragma unroll
    for (int i = 0; i < 8; i++) { pre[i] = c; c += m[i]; }

    // warp inclusive scan of per-thread counts
    int x = c;
    #pragma unroll
    for (int d = 1; d < 32; d <<= 1) {
        int y = __shfl_up_sync(0xffffffffu, x, d);
        if (lane >= d) x += y;
    }
    const int excl = x - c;
    if (lane == 31) warp_tot[w] = x;
    __syncthreads();

    if (w == 0 && lane < 8) {
        int v = warp_tot[lane];
        int xx = v;
        #pragma unroll
        for (int d = 1; d < 8; d <<= 1) {
            int y = __shfl_up_sync(0xffu, xx, d);
            if (lane >= d) xx += y;
        }
        warp_off[lane] = xx - v;
        if (lane == 7) { s_total = xx; g_cnt[b] = xx; }
    }
    __syncthreads();

    const int offs = warp_off[w] + excl;
    const int total = s_total;
    #pragma unroll
    for (int i = 0; i < 8; i++) {
        int s = base + i;
        int up = offs + pre[i];                    // unmasked before s
        if (m[i]) g_idx[b * NS + up] = s;
        else      g_idx[b * NS + total + (s - up)] = s;
    }
}

// ---------------------------------------------------------------------------
// Kernel A2: fused prep_x (blocks 0..511) + prep_w (blocks 512..575).
// ---------------------------------------------------------------------------
__global__ __launch_bounds__(256) void prep_xw(
    const float* __restrict__ X,
    const float* __restrict__ Wq, const float* __restrict__ Wk,
    const float* __restrict__ Wv, const float* __restrict__ Wo)
{
    __shared__ float t[64][65];
    const int tid = threadIdx.x;

    if (blockIdx.x < 512) {
        const int m0 = blockIdx.x * 16;
        const int bb = m0 >> 11, loc0 = m0 & (NS - 1);
        const int cnt = g_cnt[bb];
        if (loc0 >= cnt) return;
        const int* idxp = g_idx + bb * NS;

        #pragma unroll
        for (int it = 0; it < 4; it++) {
            int idx = tid + it * 256;
            int r = idx >> 6, c4 = (idx & 63) * 4;
            int src = idxp[loc0 + r];
            float4 v = *(const float4*)(X + ((size_t)bb * NS + src) * NE + c4);
            float h0,l0,h1,l1,h2,l2,h3,l3;
            split_hi_lo(v.x,h0,l0); split_hi_lo(v.y,h1,l1);
            split_hi_lo(v.z,h2,l2); split_hi_lo(v.w,h3,l3);
            size_t o = ((size_t)bb * NS + loc0 + r) * NE + c4;
            uint32_t hw[2] = { pack_bf16x2(h0,h1), pack_bf16x2(h2,h3) };
            uint32_t lw[2] = { pack_bf16x2(l0,l1), pack_bf16x2(l2,l3) };
            *(uint2*)(g_Xh + o) = *(uint2*)hw;
            *(uint2*)(g_Xl + o) = *(uint2*)lw;
        }
    } else {
        const int bidx = blockIdx.x - 512;
        const int mt = bidx >> 4;
        const int k0 = ((bidx >> 2) & 3) * 64, n0 = (bidx & 3) * 64;
        const float* Ws[4] = { Wq, Wk, Wv, Wo };
        const float* W = Ws[mt];

        #pragma unroll
        for (int it = 0; it < 16; it++) {
            int idx = tid + it * 256;
            int kk = idx >> 6, nn = idx & 63;
            t[kk][nn] = W[(k0 + kk) * NE + n0 + nn];
        }
        __syncthreads();

        #pragma unroll
        for (int it = 0; it < 2; it++) {
            int idx = tid + it * 256;
            int n = idx >> 3, c8 = (idx & 7) * 8;
            uint32_t hw[4], lw[4];
            #pragma unroll
            for (int p = 0; p < 4; p++) {
                float hi0, lo0, hi1, lo1;
                split_hi_lo(t[c8 + 2*p][n],     hi0, lo0);
                split_hi_lo(t[c8 + 2*p + 1][n], hi1, lo1);
                hw[p] = pack_bf16x2(hi0, hi1);
                lw[p] = pack_bf16x2(lo0, lo1);
            }
            size_t o = (size_t)mt * NE * NE + (size_t)(n0 + n) * NE + k0 + c8;
            *(uint4*)(g_Wth + o) = *(uint4*)hw;
            *(uint4*)(g_Wtl + o) = *(uint4*)lw;
        }
    }
}

// ---------------------------------------------------------------------------
// Kernel 1: QKV projection, one weight matrix per blockIdx.z.
// cp.async 2-stage pipeline, ldmatrix fragments.
// ---------------------------------------------------------------------------
#define QKV_SMEM_BF16 (2 * 4 * S1)    // 73728 B

__global__ __launch_bounds__(128, 3) void qkv_mma(
    const float* __restrict__ bq, const float* __restrict__ bk,
    const float* __restrict__ bv)
{
    extern __shared__ __nv_bfloat16 smb[];

    const int tid  = threadIdx.x;
    const int w4   = tid >> 5;
    const int lane = tid & 31;
    const int l4   = lane & 3;
    const int matl = lane >> 3;
    const int rowl = lane & 7;
    const int m0   = blockIdx.x * 64;
    const int h    = blockIdx.y;
    const int mt   = blockIdx.z;
    const int n0   = h * 64;

    const int bb   = m0 >> 11;
    const int loc0 = m0 & (NS - 1);
    const int cnt  = g_cnt[bb];
    if (loc0 >= cnt) return;

    const __nv_bfloat16* Xhg = g_Xh + ((size_t)bb * NS + loc0) * NE;
    const __nv_bfloat16* Xlg = g_Xl + ((size_t)bb * NS + loc0) * NE;
    const __nv_bfloat16* Wthg = g_Wth + (size_t)mt * NE * NE + (size_t)n0 * NE;
    const __nv_bfloat16* Wtlg = g_Wtl + (size_t)mt * NE * NE + (size_t)n0 * NE;

    float acc[8][4];
    #pragma unroll
    for (int j = 0; j < 8; j++)
        #pragma unroll
        for (int c = 0; c < 4; c++) acc[j][c] = 0.f;

    const int a_off = (w4 * 16 + (matl & 1) * 8 + rowl) * KPAD + (matl >> 1) * 8;
    const int b_row = (matl >> 1) * 8 + rowl;
    const int b_kh  = (matl & 1) * 8;

    const int ldr = tid >> 3, ldc = (tid & 7) * 8;

    auto load_stage = [&](int s, int k0) {
        __nv_bfloat16* sb = smb + s * 4 * S1;
        #pragma unroll
        for (int it = 0; it < 4; it++) {
            int r = ldr + it * 16;
            cpa16(sb +        r * KPAD + ldc, Xhg  + (size_t)r * NE + k0 + ldc);
            cpa16(sb + S1   + r * KPAD + ldc, Xlg  + (size_t)r * NE + k0 + ldc);
            cpa16(sb + 2*S1 + r * KPAD + ldc, Wthg + (size_t)r * NE + k0 + ldc);
            cpa16(sb + 3*S1 + r * KPAD + ldc, Wtlg + (size_t)r * NE + k0 + ldc);
        }
        CP_COMMIT();
    };

    load_stage(0, 0);
    for (int i = 0; i < 4; i++) {
        if (i < 3) { load_stage((i + 1) & 1, (i + 1) * 64); CP_WAIT1(); }
        else       { CP_WAIT0(); }
        __syncthreads();

        const __nv_bfloat16* sb  = smb + (i & 1) * 4 * S1;
        const __nv_bfloat16* Xh  = sb;
        const __nv_bfloat16* Xl  = sb + S1;
        const __nv_bfloat16* Wth = sb + 2 * S1;
        const __nv_bfloat16* Wtl = sb + 3 * S1;

        #pragma unroll
        for (int kc = 0; kc < 4; kc++) {
            uint32_t ah[4], al[4];
            ldsm4(ah, Xh + a_off + kc * 16);
            ldsm4(al, Xl + a_off + kc * 16);
            #pragma unroll
            for (int jp = 0; jp < 4; jp++) {
                int boff = (jp * 16 + b_row) * KPAD + kc * 16 + b_kh;
                uint32_t bh[4], bl[4];
                ldsm4(bh, Wth + boff);
                ldsm4(bl, Wtl + boff);
                mma16816(acc[2*jp],   ah, bh[0], bh[1]);
                mma16816(acc[2*jp],   al, bh[0], bh[1]);
                mma16816(acc[2*jp],   ah, bl[0], bl[1]);
                mma16816(acc[2*jp+1], ah, bh[2], bh[3]);
                mma16816(acc[2*jp+1], al, bh[2], bh[3]);
                mma16816(acc[2*jp+1], ah, bl[2], bl[3]);
            }
        }
        __syncthreads();
    }

    const int g = lane >> 2;
    const int s0 = loc0 + w4 * 16 + g;
    const int s1 = s0 + 8;

    if (mt == 0) {              // ---- Q: fp32 ----
        float* O0 = g_Q + (((size_t)bb * NH + h) * NS + s0) * ND;
        float* O1 = g_Q + (((size_t)bb * NH + h) * NS + s1) * ND;
        #pragma unroll
        for (int j = 0; j < 8; j++) {
            int d = j * 8 + 2 * l4;
            float bx = bq[n0 + d], by = bq[n0 + d + 1];
            float2 v0 = { acc[j][0] + bx, acc[j][1] + by };
            float2 v1 = { acc[j][2] + bx, acc[j][3] + by };
            *(float2*)(O0 + d) = v0;
            *(float2*)(O1 + d) = v1;
        }
    } else if (mt == 1) {       // ---- K: fp16 ----
        size_t o0 = (((size_t)bb * NH + h) * NS + s0) * ND;
        size_t o1 = (((size_t)bb * NH + h) * NS + s1) * ND;
        #pragma unroll
        for (int j = 0; j < 8; j++) {
            int d = j * 8 + 2 * l4;
            float bx = bk[n0 + d], by = bk[n0 + d + 1];
            *(uint32_t*)(g_Kf + o0 + d) = pack_h2(acc[j][0] + bx, acc[j][1] + by);
            *(uint32_t*)(g_Kf + o1 + d) = pack_h2(acc[j][2] + bx, acc[j][3] + by);
        }
    } else {                    // ---- V: transpose via smem, fp16 [b,h,d,i] ----
        #define VPAD 68
        float* Vb = (float*)smb;
        __syncthreads();
        #pragma unroll
        for (int j = 0; j < 8; j++) {
            int d = j * 8 + 2 * l4;
            float bx = bv[n0 + d], by = bv[n0 + d + 1];
            int sr0 = w4 * 16 + g, sr1 = sr0 + 8;
            Vb[(d    ) * VPAD + sr0] = acc[j][0] + bx;
            Vb[(d + 1) * VPAD + sr0] = acc[j][1] + by;
            Vb[(d    ) * VPAD + sr1] = acc[j][2] + bx;
            Vb[(d + 1) * VPAD + sr1] = acc[j][3] + by;
        }
        __syncthreads();
        #pragma unroll
        for (int it = 0; it < 8; it++) {
            int idx = tid + it * 128;
            int d = idx >> 4, c4 = (idx & 15) * 4;
            int s = loc0 + c4;
            size_t o = (((size_t)bb * NH + h) * ND + d) * NS + s;
            uint32_t hw[2] = { pack_h2(Vb[d * VPAD + c4],     Vb[d * VPAD + c4 + 1]),
                               pack_h2(Vb[d * VPAD + c4 + 2], Vb[d * VPAD + c4 + 3]) };
            *(uint2*)(g_Vf + o) = *(uint2*)hw;
        }
    }
}

// ---------------------------------------------------------------------------
// Kernel 2: flash attention, q-tile 64, 2 warpgroups split over K-tiles,
// cp.async double-buffered K/V, register penalties, base-2 softmax.
// ---------------------------------------------------------------------------
#define ATTN_SMEM_B (8 * S1 * 2)   // 73728 B

__global__ __launch_bounds__(256, 2) void attn_mma(
    const float* __restrict__ explore,
    const float* __restrict__ exploit)
{
    extern __shared__ __half smh[];

    const int tid  = threadIdx.x;
    const int w    = tid >> 5;
    const int wg   = w >> 2;
    const int w4   = w & 3;
    const int wtid = tid & 127;
    const int lane = tid & 31;
    const int g    = lane >> 2;
    const int l4   = lane & 3;
    const int matl = lane >> 3;
    const int rowl = lane & 7;
    const int q0   = blockIdx.x * 64;
    const int h    = blockIdx.y, b = blockIdx.z;

    const int cnt = g_cnt[b];
    if (q0 >= cnt) return;
    const int* idxp = g_idx + b * NS;
    const int NT = (cnt + 63) >> 6;

    const size_t base = ((size_t)b * NH + h) * NS * ND;
    const float* Qp = g_Q + base;
    const __half* Kp = g_Kf + base;
    const __half* Vp = g_Vf + base;

    const int r0 = w4 * 16 + g;
    const int r1 = r0 + 8;
    const int cq0 = q0 + r0, cq1 = q0 + r1;
    const int so0 = idxp[cq0], so1 = idxp[cq1];
    float rs0, rs1;
    {
        float t0 = 1.0f + 0.5f * explore[b * NS + so0] - 0.5f * exploit[b * NS + so0];
        t0 = fminf(fmaxf(t0, 0.5f), 2.0f);
        rs0 = 0.125f * LOG2E / t0;      // fold log2(e): scores in log2 units
        float t1 = 1.0f + 0.5f * explore[b * NS + so1] - 0.5f * exploit[b * NS + so1];
        t1 = fminf(fmaxf(t1, 0.5f), 2.0f);
        rs1 = 0.125f * LOG2E / t1;
    }

    uint32_t qf[4][4];
    #pragma unroll
    for (int kc = 0; kc < 4; kc++) {
        int d0 = kc * 16 + l4 * 2;
        const float2 a00 = *(const float2*)(Qp + (size_t)cq0 * ND + d0);
        const float2 a10 = *(const float2*)(Qp + (size_t)cq1 * ND + d0);
        const float2 a01 = *(const float2*)(Qp + (size_t)cq0 * ND + d0 + 8);
        const float2 a11 = *(const float2*)(Qp + (size_t)cq1 * ND + d0 + 8);
        qf[kc][0] = pack_h2(a00.x * rs0, a00.y * rs0);
        qf[kc][1] = pack_h2(a10.x * rs1, a10.y * rs1);
        qf[kc][2] = pack_h2(a01.x * rs0, a01.y * rs0);
        qf[kc][3] = pack_h2(a11.x * rs1, a11.y * rs1);
    }

    float oacc[8][4];
    #pragma unroll
    for (int j = 0; j < 8; j++)
        #pragma unroll
        for (int c = 0; c < 4; c++) oacc[j][c] = 0.f;
    float lsum0 = 0.f, lsum1 = 0.f;

    const int b_row = (matl >> 1) * 8 + rowl;
    const int b_kh  = (matl & 1) * 8;
    const int ldr = wtid >> 3, ldc = (wtid & 7) * 8;

    const int ntw = (NT - wg + 1) >> 1;

    auto load_tile = [&](int buf, int kt) {
        __half* Kd = smh + ((size_t)(wg * 2 + buf)) * S1;
        __half* Vd = smh + ((size_t)(4 + wg * 2 + buf)) * S1;
        const int kk0 = kt * 64;
        #pragma unroll
        for (int it = 0; it < 4; it++) {
            int r = ldr + it * 16;
            cpa16(Kd + r * KPAD + ldc, Kp + (size_t)(kk0 + r) * ND + ldc);
            cpa16(Vd + r * KPAD + ldc, Vp + (size_t)r * NS + kk0 + ldc);
        }
        CP_COMMIT();
    };

    if (ntw > 0) load_tile(0, wg);
    for (int ii = 0; ii < ntw; ii++) {
        const int kt = wg + 2 * ii;
        const int kk0 = kt * 64;
        if (ii + 1 < ntw) { load_tile((ii + 1) & 1, kt + 2); CP_WAIT1(); }
        else              { CP_WAIT0(); }
        asm volatile("bar.sync %0, %1;" :: "r"(wg + 1), "r"(128) : "memory");

        const __half* Ksw = smh + ((size_t)(wg * 2 + (ii & 1))) * S1;
        const __half* Vsw = smh + ((size_t)(4 + wg * 2 + (ii & 1))) * S1;

        float sacc[8][4];
        #pragma unroll
        for (int j = 0; j < 8; j++)
            #pragma unroll
            for (int c = 0; c < 4; c++) sacc[j][c] = 0.f;

        #pragma unroll
        for (int kc = 0; kc < 4; kc++) {
            #pragma unroll
            for (int jp = 0; jp < 4; jp++) {
                uint32_t kb[4];
                ldsm4(kb, Ksw + (jp * 16 + b_row) * KPAD + kc * 16 + b_kh);
                mma16816h(sacc[2*jp],   qf[kc], kb[0], kb[1]);
                mma16816h(sacc[2*jp+1], qf[kc], kb[2], kb[3]);
            }
        }

        uint32_t ps[8][2];
        #pragma unroll
        for (int j = 0; j < 8; j++) {
            int col = kk0 + j * 8 + l4 * 2;
            float px = (col     < cnt) ? -14.0f : -1e30f;   // log2-units shift
            float py = (col + 1 < cnt) ? -14.0f : -1e30f;
            float p0 = ex2(sacc[j][0] + px);
            float p1 = ex2(sacc[j][1] + py);
            float p2 = ex2(sacc[j][2] + px);
            float p3 = ex2(sacc[j][3] + py);
            lsum0 += p0 + p1;
            lsum1 += p2 + p3;
            ps[j][0] = pack_h2(p0, p1);
            ps[j][1] = pack_h2(p2, p3);
        }

        #pragma unroll
        for (int kc = 0; kc < 4; kc++) {
            uint32_t Af[4] = { ps[2*kc][0], ps[2*kc][1], ps[2*kc+1][0], ps[2*kc+1][1] };
            #pragma unroll
            for (int jp = 0; jp < 4; jp++) {
                uint32_t vb[4];
                ldsm4(vb, Vsw + (jp * 16 + b_row) * KPAD + kc * 16 + b_kh);
                mma16816h(oacc[2*jp],   Af, vb[0], vb[1]);
                mma16816h(oacc[2*jp+1], Af, vb[2], vb[3]);
            }
        }
        asm volatile("bar.sync %0, %1;" :: "r"(wg + 1), "r"(128) : "memory");
    }

    lsum0 += __shfl_xor_sync(0xffffffffu, lsum0, 1);
    lsum0 += __shfl_xor_sync(0xffffffffu, lsum0, 2);
    lsum1 += __shfl_xor_sync(0xffffffffu, lsum1, 1);
    lsum1 += __shfl_xor_sync(0xffffffffu, lsum1, 2);

    // ---- combine wg partials through smem (overlay on wg0 K buffers) ----
    __syncthreads();
    float* Ob = (float*)smh;                 // 64 x 66 floats
    float* Lb = Ob + 64 * 66;                // 64 floats
    if (wg == 1) {
        #pragma unroll
        for (int j = 0; j < 8; j++) {
            int col = j * 8 + 2 * l4;
            Ob[r0 * 66 + col]     = oacc[j][0];
            Ob[r0 * 66 + col + 1] = oacc[j][1];
            Ob[r1 * 66 + col]     = oacc[j][2];
            Ob[r1 * 66 + col + 1] = oacc[j][3];
        }
        if (l4 == 0) { Lb[r0] = lsum0; Lb[r1] = lsum1; }
    }
    __syncthreads();
    if (wg == 0) {
        lsum0 += Lb[r0];
        lsum1 += Lb[r1];
        float inv0 = (lsum0 > 0.f) ? 1.f / lsum0 : 0.f;
        float inv1 = (lsum1 > 0.f) ? 1.f / lsum1 : 0.f;
        if (cq0 < cnt) {
            size_t o0 = base + (size_t)cq0 * ND;
            #pragma unroll
            for (int j = 0; j < 8; j++) {
                int col = j * 8 + 2 * l4;
                float v0 = (oacc[j][0] + Ob[r0 * 66 + col])     * inv0;
                float v1 = (oacc[j][1] + Ob[r0 * 66 + col + 1]) * inv0;
                float h0,l0,h1,l1;
                split_hi_lo(v0, h0, l0); split_hi_lo(v1, h1, l1);
                *(uint32_t*)(g_AOh + o0 + col) = pack_bf16x2(h0, h1);
                *(uint32_t*)(g_AOl + o0 + col) = pack_bf16x2(l0, l1);
            }
        }
        if (cq1 < cnt) {
            size_t o1 = base + (size_t)cq1 * ND;
            #pragma unroll
            for (int j = 0; j < 8; j++) {
                int col = j * 8 + 2 * l4;
                float v0 = (oacc[j][2] + Ob[r1 * 66 + col])     * inv1;
                float v1 = (oacc[j][3] + Ob[r1 * 66 + col + 1]) * inv1;
                float h0,l0,h1,l1;
                split_hi_lo(v0, h0, l0); split_hi_lo(v1, h1, l1);
                *(uint32_t*)(g_AOh + o1 + col) = pack_bf16x2(h0, h1);
                *(uint32_t*)(g_AOl + o1 + col) = pack_bf16x2(l0, l1);
            }
        }
    }
}

// ---------------------------------------------------------------------------
// Kernel 3: output projection + masked-row zeroing (tail/partial blocks).
// ---------------------------------------------------------------------------
#define OP_SMEM_BF16 (2 * 4 * S1)    // 73728 B

__global__ __launch_bounds__(128, 3) void out_proj_mma(
    const float* __restrict__ bo,
    float* __restrict__ out)
{
    extern __shared__ __nv_bfloat16 smb[];

    const int tid  = threadIdx.x;
    const int w4   = tid >> 5;
    const int lane = tid & 31;
    const int l4   = lane & 3;
    const int matl = lane >> 3;
    const int rowl = lane & 7;
    const int m0   = blockIdx.x * 64;
    const int n0   = blockIdx.y * 64;

    const int bb   = m0 >> 11;
    const int loc0 = m0 & (NS - 1);
    const int cnt  = g_cnt[bb];
    const int* idxp = g_idx + bb * NS;

    if (loc0 >= cnt) {
        #pragma unroll
        for (int it = 0; it < 8; it++) {
            int idx = tid + it * 128;
            int r = idx >> 4, c4 = (idx & 15) * 4;
            int row = bb * NS + idxp[loc0 + r];
            float4 z = {0.f, 0.f, 0.f, 0.f};
            *(float4*)(out + (size_t)row * NE + n0 + c4) = z;
        }
        return;
    }

    const __nv_bfloat16* Wthg = g_Wth + (size_t)3 * NE * NE + (size_t)n0 * NE;
    const __nv_bfloat16* Wtlg = g_Wtl + (size_t)3 * NE * NE + (size_t)n0 * NE;

    float acc[8][4];
    #pragma unroll
    for (int j = 0; j < 8; j++)
        #pragma unroll
        for (int c = 0; c < 4; c++) acc[j][c] = 0.f;

    const int a_off = (w4 * 16 + (matl & 1) * 8 + rowl) * KPAD + (matl >> 1) * 8;
    const int b_row = (matl >> 1) * 8 + rowl;
    const int b_kh  = (matl & 1) * 8;
    const int ldr = tid >> 3, ldc = (tid & 7) * 8;

    auto load_stage = [&](int s, int k0) {
        __nv_bfloat16* sb = smb + s * 4 * S1;
        const int hh = k0 >> 6;
        const __nv_bfloat16* Ah = g_AOh + (((size_t)bb * NH + hh) * NS + loc0) * ND;
        const __nv_bfloat16* Al = g_AOl + (((size_t)bb * NH + hh) * NS + loc0) * ND;
        #pragma unroll
        for (int it = 0; it < 4; it++) {
            int r = ldr + it * 16;
            cpa16(sb +        r * KPAD + ldc, Ah + (size_t)r * ND + ldc);
            cpa16(sb + S1   + r * KPAD + ldc, Al + (size_t)r * ND + ldc);
            cpa16(sb + 2*S1 + r * KPAD + ldc, Wthg + (size_t)r * NE + k0 + ldc);
            cpa16(sb + 3*S1 + r * KPAD + ldc, Wtlg + (size_t)r * NE + k0 + ldc);
        }
        CP_COMMIT();
    };

    load_stage(0, 0);
    for (int i = 0; i < 4; i++) {
        if (i < 3) { load_stage((i + 1) & 1, (i + 1) * 64); CP_WAIT1(); }
        else       { CP_WAIT0(); }
        __syncthreads();

        const __nv_bfloat16* sb  = smb + (i & 1) * 4 * S1;
        const __nv_bfloat16* Xh  = sb;
        const __nv_bfloat16* Xl  = sb + S1;
        const __nv_bfloat16* Wth = sb + 2 * S1;
        const __nv_bfloat16* Wtl = sb + 3 * S1;

        #pragma unroll
        for (int kc = 0; kc < 4; kc++) {
            uint32_t ah[4], al[4];
            ldsm4(ah, Xh + a_off + kc * 16);
            ldsm4(al, Xl + a_off + kc * 16);
            #pragma unroll
            for (int jp = 0; jp < 4; jp++) {
                int boff = (jp * 16 + b_row) * KPAD + kc * 16 + b_kh;
                uint32_t bh[4], bl[4];
                ldsm4(bh, Wth + boff);
                ldsm4(bl, Wtl + boff);
                mma16816(acc[2*jp],   ah, bh[0], bh[1]);
                mma16816(acc[2*jp],   al, bh[0], bh[1]);
                mma16816(acc[2*jp],   ah, bl[0], bl[1]);
                mma16816(acc[2*jp+1], ah, bh[2], bh[3]);
                mma16816(acc[2*jp+1], al, bh[2], bh[3]);
                mma16816(acc[2*jp+1], ah, bl[2], bl[3]);
            }
        }
        __syncthreads();
    }

    const int g = lane >> 2;
    const int lr0 = loc0 + w4 * 16 + g;
    const int lr1 = lr0 + 8;
    {
        int row = bb * NS + idxp[lr0];
        bool live = (lr0 < cnt);
        #pragma unroll
        for (int j = 0; j < 8; j++) {
            int d = j * 8 + 2 * l4;
            float2 v = { live ? acc[j][0] + bo[n0 + d]     : 0.f,
                         live ? acc[j][1] + bo[n0 + d + 1] : 0.f };
            *(float2*)(out + (size_t)row * NE + n0 + d) = v;
        }
    }
    {
        int row = bb * NS + idxp[lr1];
        bool live = (lr1 < cnt);
        #pragma unroll
        for (int j = 0; j < 8; j++) {
            int d = j * 8 + 2 * l4;
            float2 v = { live ? acc[j][2] + bo[n0 + d]     : 0.f,
                         live ? acc[j][3] + bo[n0 + d + 1] : 0.f };
            *(float2*)(out + (size_t)row * NE + n0 + d) = v;
        }
    }
}

// ---------------------------------------------------------------------------
extern "C" void kernel_launch(void* const* d_in, const int* in_sizes, int n_in,
                              void* d_out, int out_size)
{
    const float* his     = (const float*)d_in[0];
    const int*   mask    = (const int*)d_in[1];
    const float* explore = (const float*)d_in[2];
    const float* exploit = (const float*)d_in[3];
    const float* Wq = (const float*)d_in[4];
    const float* bq = (const float*)d_in[5];
    const float* Wk = (const float*)d_in[6];
    const float* bk = (const float*)d_in[7];
    const float* Wv = (const float*)d_in[8];
    const float* bv = (const float*)d_in[9];
    const float* Wo = (const float*)d_in[10];
    const float* bo = (const float*)d_in[11];
    float* out = (float*)d_out;

    const int qkv_smem  = QKV_SMEM_BF16 * 2;    // 73728 B
    const int op_smem   = OP_SMEM_BF16 * 2;     // 73728 B
    const int attn_smem = ATTN_SMEM_B;          // 73728 B
    static bool attr_done = false;
    if (!attr_done) {
        cudaFuncSetAttribute(qkv_mma, cudaFuncAttributeMaxDynamicSharedMemorySize, qkv_smem);
        cudaFuncSetAttribute(out_proj_mma, cudaFuncAttributeMaxDynamicSharedMemorySize, op_smem);
        cudaFuncSetAttribute(attn_mma, cudaFuncAttributeMaxDynamicSharedMemorySize, attn_smem);
        attr_done = true;
    }

    // single stream, 5 linear nodes
    build_idx<<<NB, 256>>>(mask);
    prep_xw<<<576, 256>>>(his, Wq, Wk, Wv, Wo);
    qkv_mma<<<dim3(NB * NS / 64, NH, 3), 128, qkv_smem>>>(bq, bk, bv);
    attn_mma<<<dim3(NS / 64, NH, NB), 256, attn_smem>>>(explore, exploit);
    out_proj_mma<<<dim3(NB * NS / 64, 4), 128, op_smem>>>(bo, out);
}